// round 8
// baseline (speedup 1.0000x reference)
#include <cuda_runtime.h>
#include <cuda_bf16.h>
#include <math.h>

// ---------------- problem constants ----------------
#define NMAX 10000
#define EMAX 320000
#define MMAX (EMAX + NMAX)   // edges + self loops

// ---------------- device scratch (float) ----------------
__device__ __align__(16) float g_H0 [NMAX * 512];   // x @ W0^T (fp32, for attn0 + agg0 gather)
__device__ __align__(16) float g_H1 [NMAX * 128];   // H0A @ W1^T
__device__ __align__(16) float g_H1A[NMAX * 128];   // elu(agg1 + b1)
__device__ __align__(16) float g_AS0[NMAX * 4];
__device__ __align__(16) float g_AD0[NMAX * 4];
__device__ __align__(16) float g_AS1[NMAX];
__device__ __align__(16) float g_AD1[NMAX];
__device__ __align__(16) float g_S1 [NMAX];
__device__ __align__(16) float g_S2 [NMAX];
__device__ __align__(16) float g_V  [260];          // v1[128], v2[128], c
__device__ __align__(16) int   g_deg[NMAX];
__device__ __align__(16) int   g_off[NMAX + 1];
__device__ __align__(16) int   g_cur[NMAX];
__device__ __align__(16) int   g_srt[MMAX];

// ---------------- device scratch (packed bf16 hi/lo pairs, 2 k-values per uint) ----------------
__device__ __align__(16) unsigned g_XH  [NMAX * 64];    // x split (K=128 -> 64 pairs)
__device__ __align__(16) unsigned g_XL  [NMAX * 64];
__device__ __align__(16) unsigned g_W0H [512 * 64];
__device__ __align__(16) unsigned g_W0L [512 * 64];
__device__ __align__(16) unsigned g_W1H [128 * 256];    // K=512 -> 256 pairs
__device__ __align__(16) unsigned g_W1L [128 * 256];
__device__ __align__(16) unsigned g_H0AH[NMAX * 256];   // H0A split (512 ch -> 256 pairs)
__device__ __align__(16) unsigned g_H0AL[NMAX * 256];

// float buffer ids
#define B_H0   0
#define B_H1   2
#define B_H1A  3
#define B_AS0  5
#define B_AD0  6
#define B_AS1  7
#define B_AD1  8
#define B_S1   9
#define B_S2   10
#define B_V    11
#define B_EXT  (-1)

__device__ __forceinline__ float* buf_sel(int id) {
    switch (id) {
        case B_H0:  return g_H0;
        case B_H1:  return g_H1;
        case B_H1A: return g_H1A;
        case B_AS0: return g_AS0;
        case B_AD0: return g_AD0;
        case B_AS1: return g_AS1;
        case B_AD1: return g_AD1;
        case B_S1:  return g_S1;
        case B_V:   return g_V;
        default:    return g_S2;
    }
}

// packed buffer ids
#define U_XH   0
#define U_XL   1
#define U_W0H  2
#define U_W0L  3
#define U_W1H  4
#define U_W1L  5
#define U_H0AH 6
#define U_H0AL 7

__device__ __forceinline__ unsigned* ubuf_sel(int id) {
    switch (id) {
        case U_XH:   return g_XH;
        case U_XL:   return g_XL;
        case U_W0H:  return g_W0H;
        case U_W0L:  return g_W0L;
        case U_W1H:  return g_W1H;
        case U_W1L:  return g_W1L;
        case U_H0AH: return g_H0AH;
        default:     return g_H0AL;
    }
}

__device__ __forceinline__ unsigned pack_bf2(float a, float b) {
    __nv_bfloat162 p = __floats2bfloat162_rn(a, b);
    return *reinterpret_cast<unsigned*>(&p);
}

// ---------------- CSR build kernels ----------------
__global__ void zero_deg_kernel(int n) {
    int i = blockIdx.x * blockDim.x + threadIdx.x;
    if (i < n) g_deg[i] = 0;
}

__global__ void hist_kernel(const int* __restrict__ ei, int E, int n) {
    int e = blockIdx.x * blockDim.x + threadIdx.x;
    int M = E + n;
    if (e >= M) return;
    int dst = (e < E) ? ei[E + e] : (e - E);
    if ((unsigned)dst < (unsigned)n)
        atomicAdd(&g_deg[dst], 1);
}

__global__ void scan_kernel(int n) {
    __shared__ int sm[1024];
    int t = threadIdx.x;
    int chunk = (n + 1023) >> 10;
    int b = t * chunk;
    int e = min(n, b + chunk);
    int s = 0;
    for (int i = b; i < e; i++) s += g_deg[i];
    sm[t] = s;
    __syncthreads();
    for (int o = 1; o < 1024; o <<= 1) {
        int v = (t >= o) ? sm[t - o] : 0;
        __syncthreads();
        sm[t] += v;
        __syncthreads();
    }
    int run = sm[t] - s;
    for (int i = b; i < e; i++) {
        g_off[i] = run;
        g_cur[i] = run;
        run += g_deg[i];
    }
    if (t == 1023) g_off[n] = sm[1023];
}

__global__ void scatter_kernel(const int* __restrict__ ei, int E, int n) {
    int e = blockIdx.x * blockDim.x + threadIdx.x;
    int M = E + n;
    if (e >= M) return;
    int src, dst;
    if (e < E) { src = ei[e]; dst = ei[E + e]; }
    else       { src = e - E; dst = e - E; }
    if ((unsigned)dst >= (unsigned)n || (unsigned)src >= (unsigned)n) return;
    int pos = atomicAdd(&g_cur[dst], 1);
    if (pos < MMAX) g_srt[pos] = src;
}

// ---------------- operand split: fp32 -> packed bf16 hi / lo ----------------
__global__ void split_kernel(const float* __restrict__ X, int hid, int lid, int total_pairs) {
    unsigned* H = ubuf_sel(hid);
    unsigned* L = ubuf_sel(lid);
    int i = blockIdx.x * blockDim.x + threadIdx.x;
    if (i >= total_pairs) return;
    float2 v = ((const float2*)X)[i];
    float hx = __bfloat162float(__float2bfloat16_rn(v.x));
    float hy = __bfloat162float(__float2bfloat16_rn(v.y));
    H[i] = pack_bf2(hx, hy);
    L[i] = pack_bf2(v.x - hx, v.y - hy);
}

// ---------------- v-vectors: v1 = Wout^T w1, v2 = Wout^T w2, c = bout.(w1+w2) ----------------
__global__ void vec_kernel(const float* __restrict__ Wout, const float* __restrict__ bout,
                           const float* __restrict__ Wedge) {
    int k = threadIdx.x;   // 128
    float a1 = 0.f, a2 = 0.f;
    for (int j = 0; j < 128; j++) {
        float wo = Wout[j * 128 + k];
        a1 += wo * Wedge[j];
        a2 += wo * Wedge[128 + j];
    }
    g_V[k] = a1;
    g_V[128 + k] = a2;
    if (k == 0) {
        float c = 0.f;
        for (int j = 0; j < 128; j++) c += bout[j] * (Wedge[j] + Wedge[128 + j]);
        g_V[256] = c;
    }
}

// ---------------- bf16x3 TC GEMM on pre-split operands: C[M,N] = A[M,K]*B[N,K]^T (+bias) ----------------
// C += Ahi*Bhi + Ahi*Blo + Alo*Bhi. Tile 128x64, TBK=32 (16 pairs), 256 thr = 8 warps (2m x 4n).
// Row stride 20 uint -> fragment LDS is a perfect 32-bank permutation.
#define TBM 128
#define TBN 64
#define KP  16            // packed pairs per tile (32 k)
#define SSTR (KP + 4)     // 20

__device__ __forceinline__ void mma_bf16(float acc[4], unsigned a0, unsigned a1,
                                         unsigned a2, unsigned a3,
                                         unsigned b0, unsigned b1) {
    asm volatile(
        "mma.sync.aligned.m16n8k16.row.col.f32.bf16.bf16.f32 "
        "{%0,%1,%2,%3}, {%4,%5,%6,%7}, {%8,%9}, {%0,%1,%2,%3};"
        : "+f"(acc[0]), "+f"(acc[1]), "+f"(acc[2]), "+f"(acc[3])
        : "r"(a0), "r"(a1), "r"(a2), "r"(a3), "r"(b0), "r"(b1));
}

__global__ void __launch_bounds__(256)
gemm_tc_kernel(int ahid, int alid, int bhid, int blid,
               const float* __restrict__ bias, int cid,
               int M, int N, int K) {
    const unsigned* AH = ubuf_sel(ahid);
    const unsigned* AL = ubuf_sel(alid);
    const unsigned* BH = ubuf_sel(bhid);
    const unsigned* BL = ubuf_sel(blid);
    float* C = buf_sel(cid);
    int Kp = K >> 1;

    __shared__ unsigned AsH[TBM * SSTR];
    __shared__ unsigned AsL[TBM * SSTR];
    __shared__ unsigned BsH[TBN * SSTR];
    __shared__ unsigned BsL[TBN * SSTR];

    int tid = threadIdx.x;
    int warp = tid >> 5, lane = tid & 31;
    int wm = warp >> 2;          // 0..1
    int wn = warp & 3;           // 0..3
    int bm = blockIdx.y * TBM;
    int bn = blockIdx.x * TBN;

    int lr = tid >> 3;           // 0..31 (load row)
    int lc = tid & 7;            // 0..7  (2 packed pairs)

    float acc[4][2][4];
#pragma unroll
    for (int mt = 0; mt < 4; mt++)
#pragma unroll
        for (int nt = 0; nt < 2; nt++)
#pragma unroll
            for (int r = 0; r < 4; r++) acc[mt][nt][r] = 0.f;

    int qrow = lane >> 2;        // 0..7
    int qcol = lane & 3;         // 0..3

    for (int k0p = 0; k0p < Kp; k0p += KP) {
        // A tile: 128 rows x 16 pairs
#pragma unroll
        for (int i = 0; i < 4; i++) {
            int rl = lr + 32 * i;
            int rg = bm + rl;
            uint2 h = {0u, 0u}, l = {0u, 0u};
            if (rg < M) {
                h = *(const uint2*)&AH[(size_t)rg * Kp + k0p + lc * 2];
                l = *(const uint2*)&AL[(size_t)rg * Kp + k0p + lc * 2];
            }
            unsigned* dH = &AsH[rl * SSTR + lc * 2];
            unsigned* dL = &AsL[rl * SSTR + lc * 2];
            dH[0] = h.x; dH[1] = h.y;
            dL[0] = l.x; dL[1] = l.y;
        }
        // B tile: 64 rows x 16 pairs (N multiple of 64 -> no guard)
#pragma unroll
        for (int i = 0; i < 2; i++) {
            int rl = lr + 32 * i;
            uint2 h = *(const uint2*)&BH[(size_t)(bn + rl) * Kp + k0p + lc * 2];
            uint2 l = *(const uint2*)&BL[(size_t)(bn + rl) * Kp + k0p + lc * 2];
            unsigned* dH = &BsH[rl * SSTR + lc * 2];
            unsigned* dL = &BsL[rl * SSTR + lc * 2];
            dH[0] = h.x; dH[1] = h.y;
            dL[0] = l.x; dL[1] = l.y;
        }
        __syncthreads();

#pragma unroll
        for (int ks = 0; ks < 2; ks++) {
            int kb = ks * 8;     // pair offset of this k16 slab
            unsigned bh[2][2], bl[2][2];
#pragma unroll
            for (int nt = 0; nt < 2; nt++) {
                int nn = wn * 16 + nt * 8 + qrow;
                bh[nt][0] = BsH[nn * SSTR + kb + qcol];
                bh[nt][1] = BsH[nn * SSTR + kb + qcol + 4];
                bl[nt][0] = BsL[nn * SSTR + kb + qcol];
                bl[nt][1] = BsL[nn * SSTR + kb + qcol + 4];
            }
#pragma unroll
            for (int mt = 0; mt < 4; mt++) {
                int mm = wm * 64 + mt * 16 + qrow;
                unsigned ah0 = AsH[mm * SSTR + kb + qcol];
                unsigned ah1 = AsH[(mm + 8) * SSTR + kb + qcol];
                unsigned ah2 = AsH[mm * SSTR + kb + qcol + 4];
                unsigned ah3 = AsH[(mm + 8) * SSTR + kb + qcol + 4];
                unsigned al0 = AsL[mm * SSTR + kb + qcol];
                unsigned al1 = AsL[(mm + 8) * SSTR + kb + qcol];
                unsigned al2 = AsL[mm * SSTR + kb + qcol + 4];
                unsigned al3 = AsL[(mm + 8) * SSTR + kb + qcol + 4];
#pragma unroll
                for (int nt = 0; nt < 2; nt++) {
                    mma_bf16(acc[mt][nt], ah0, ah1, ah2, ah3, bh[nt][0], bh[nt][1]);
                    mma_bf16(acc[mt][nt], ah0, ah1, ah2, ah3, bl[nt][0], bl[nt][1]);
                    mma_bf16(acc[mt][nt], al0, al1, al2, al3, bh[nt][0], bh[nt][1]);
                }
            }
        }
        __syncthreads();
    }

#pragma unroll
    for (int mt = 0; mt < 4; mt++) {
#pragma unroll
        for (int nt = 0; nt < 2; nt++) {
            int row = bm + wm * 64 + mt * 16 + qrow;
            int col = bn + wn * 16 + nt * 8 + qcol * 2;
            float b0 = 0.f, b1 = 0.f;
            if (bias) { b0 = bias[col]; b1 = bias[col + 1]; }
            if (row < M) {
                float2 o = {acc[mt][nt][0] + b0, acc[mt][nt][1] + b1};
                *(float2*)&C[(size_t)row * N + col] = o;
            }
            if (row + 8 < M) {
                float2 o = {acc[mt][nt][2] + b0, acc[mt][nt][3] + b1};
                *(float2*)&C[(size_t)(row + 8) * N + col] = o;
            }
        }
    }
}

// ---------------- attention coefficients: out[n,h] = sum_c H[n,h,c]*att[h,c] ----------------
__global__ void attn_coef_kernel(int hid, const float* __restrict__ atts_ext,
                                 const float* __restrict__ attd_ext,
                                 int attid,       // if >= 0: atts = buf_sel(attid), attd = atts+128
                                 int osid, int odid, int heads) {
    const float* H = buf_sel(hid);
    const float* atts = (attid >= 0) ? buf_sel(attid) : atts_ext;
    const float* attd = (attid >= 0) ? buf_sel(attid) + 128 : attd_ext;
    float* osrc = buf_sel(osid);
    float* odst = buf_sel(odid);

    int node = blockIdx.x;
    int t = threadIdx.x;            // 128
    int w = t >> 5, lane = t & 31;
    int Ct = heads * 128;
    float ps[4] = {0.f, 0.f, 0.f, 0.f}, pd[4] = {0.f, 0.f, 0.f, 0.f};
    for (int k = 0; k < heads; k++) {
        float h = H[(size_t)node * Ct + k * 128 + t];
        ps[k] = h * atts[k * 128 + t];
        pd[k] = h * attd[k * 128 + t];
    }
#pragma unroll
    for (int o = 16; o; o >>= 1) {
#pragma unroll
        for (int k = 0; k < 4; k++) {
            ps[k] += __shfl_xor_sync(~0u, ps[k], o);
            pd[k] += __shfl_xor_sync(~0u, pd[k], o);
        }
    }
    __shared__ float ss[4][4], sd[4][4];
    if (lane == 0) {
#pragma unroll
        for (int k = 0; k < 4; k++) { ss[w][k] = ps[k]; sd[w][k] = pd[k]; }
    }
    __syncthreads();
    if (t < heads) {
        osrc[node * heads + t] = ss[0][t] + ss[1][t] + ss[2][t] + ss[3][t];
        odst[node * heads + t] = sd[0][t] + sd[1][t] + sd[2][t] + sd[3][t];
    }
}

// ---------------- layer-0 aggregation: writes H0A directly as packed bf16 hi/lo ----------------
__global__ void agg0_kernel(const float* __restrict__ b0) {
    int node = blockIdx.x;
    int t = threadIdx.x;            // 128
    int w = t >> 5;
    int beg = g_off[node], end = g_off[node + 1];

    float adsth = g_AD0[node * 4 + w];

    float4 acc = {0.f, 0.f, 0.f, 0.f};
    float denom = 0.f;
    for (int i = beg; i < end; i++) {
        int s = g_srt[i];
        float a = g_AS0[s * 4 + w] + adsth;
        a = (a >= 0.f) ? a : 0.2f * a;
        float ex = __expf(a);
        denom += ex;
        float4 v = *(const float4*)&g_H0[(size_t)s * 512 + t * 4];
        acc.x += ex * v.x; acc.y += ex * v.y; acc.z += ex * v.z; acc.w += ex * v.w;
    }
    float inv = 1.f / (denom + 1e-16f);
    float4 bb = *(const float4*)&b0[t * 4];
    float4 o4;
    o4.x = acc.x * inv + bb.x;
    o4.y = acc.y * inv + bb.y;
    o4.z = acc.z * inv + bb.z;
    o4.w = acc.w * inv + bb.w;
    o4.x = (o4.x > 0.f) ? o4.x : expm1f(o4.x);
    o4.y = (o4.y > 0.f) ? o4.y : expm1f(o4.y);
    o4.z = (o4.z > 0.f) ? o4.z : expm1f(o4.z);
    o4.w = (o4.w > 0.f) ? o4.w : expm1f(o4.w);

    // split + pack (GEMM1 consumes only the split form)
    float hx = __bfloat162float(__float2bfloat16_rn(o4.x));
    float hy = __bfloat162float(__float2bfloat16_rn(o4.y));
    float hz = __bfloat162float(__float2bfloat16_rn(o4.z));
    float hw = __bfloat162float(__float2bfloat16_rn(o4.w));
    size_t base = (size_t)node * 256 + t * 2;
    g_H0AH[base]     = pack_bf2(hx, hy);
    g_H0AH[base + 1] = pack_bf2(hz, hw);
    g_H0AL[base]     = pack_bf2(o4.x - hx, o4.y - hy);
    g_H0AL[base + 1] = pack_bf2(o4.z - hz, o4.w - hw);
}

// ---------------- layer-1 aggregation ----------------
__global__ void agg1_kernel(const float* __restrict__ b1, int n) {
    int w = threadIdx.x >> 5, lane = threadIdx.x & 31;
    int node = blockIdx.x * 4 + w;
    if (node >= n) return;
    int beg = g_off[node], end = g_off[node + 1];
    float adv = g_AD1[node];

    float4 acc = {0.f, 0.f, 0.f, 0.f};
    float denom = 0.f;
    for (int i = beg; i < end; i++) {
        int s = g_srt[i];
        float a = g_AS1[s] + adv;
        a = (a >= 0.f) ? a : 0.2f * a;
        float ex = __expf(a);
        denom += ex;
        float4 v = *(const float4*)&g_H1[(size_t)s * 128 + lane * 4];
        acc.x += ex * v.x; acc.y += ex * v.y; acc.z += ex * v.z; acc.w += ex * v.w;
    }
    float inv = 1.f / (denom + 1e-16f);
    float4 bb = *(const float4*)&b1[lane * 4];
    float4 o4;
    o4.x = acc.x * inv + bb.x;
    o4.y = acc.y * inv + bb.y;
    o4.z = acc.z * inv + bb.z;
    o4.w = acc.w * inv + bb.w;
    o4.x = (o4.x > 0.f) ? o4.x : expm1f(o4.x);
    o4.y = (o4.y > 0.f) ? o4.y : expm1f(o4.y);
    o4.z = (o4.z > 0.f) ? o4.z : expm1f(o4.z);
    o4.w = (o4.w > 0.f) ? o4.w : expm1f(o4.w);
    *(float4*)&g_H1A[(size_t)node * 128 + lane * 4] = o4;
}

// ---------------- final outer sum: out[i*n+j] = s1[i] + s2[j] + c + bedge ----------------
__global__ void outer_kernel(const float* __restrict__ bedge, float* __restrict__ out, int n) {
    int i = blockIdx.x;
    float v = g_S1[i] + bedge[0] + g_V[256];
    float* row = out + (size_t)i * n;
    int n4 = n >> 2;
    const float4* s24 = (const float4*)g_S2;
    for (int j = threadIdx.x; j < n4; j += blockDim.x) {
        float4 b = s24[j];
        float4 o = {v + b.x, v + b.y, v + b.z, v + b.w};
        ((float4*)row)[j] = o;
    }
    for (int j = (n4 << 2) + threadIdx.x; j < n; j += blockDim.x)
        row[j] = v + g_S2[j];
}

// ---------------- host launcher ----------------
extern "C" void kernel_launch(void* const* d_in, const int* in_sizes, int n_in,
                              void* d_out, int out_size) {
    const float* x        = (const float*)d_in[0];
    const int*   ei       = (const int*)d_in[1];     // int32
    const float* W0       = (const float*)d_in[2];
    const float* att_src0 = (const float*)d_in[3];
    const float* att_dst0 = (const float*)d_in[4];
    const float* b0       = (const float*)d_in[5];
    const float* W1       = (const float*)d_in[6];
    const float* att_src1 = (const float*)d_in[7];
    const float* att_dst1 = (const float*)d_in[8];
    const float* b1       = (const float*)d_in[9];
    const float* Wout     = (const float*)d_in[10];
    const float* bout     = (const float*)d_in[11];
    const float* Wedge    = (const float*)d_in[12];
    const float* bedge    = (const float*)d_in[13];
    float* out = (float*)d_out;

    int n = in_sizes[0] / 128;
    int E = in_sizes[1] / 2;
    int M = E + n;

    // Fork side stream: CSR build + v-vector kernel overlap the main chain.
    cudaStream_t side;
    cudaStreamCreateWithFlags(&side, cudaStreamNonBlocking);
    cudaEvent_t evFork, evJoin;
    cudaEventCreateWithFlags(&evFork, cudaEventDisableTiming);
    cudaEventCreateWithFlags(&evJoin, cudaEventDisableTiming);

    cudaEventRecord(evFork, (cudaStream_t)0);
    cudaStreamWaitEvent(side, evFork, 0);

    zero_deg_kernel<<<(n + 255) / 256, 256, 0, side>>>(n);
    hist_kernel<<<(M + 255) / 256, 256, 0, side>>>(ei, E, n);
    scan_kernel<<<1, 1024, 0, side>>>(n);
    scatter_kernel<<<(M + 255) / 256, 256, 0, side>>>(ei, E, n);
    vec_kernel<<<1, 128, 0, side>>>(Wout, bout, Wedge);
    cudaEventRecord(evJoin, side);

    // ---- operand splits (main stream; cheap, feed GEMM0/GEMM1) ----
    {
        int p = n * 64;          // x: n x 128 -> 64 pairs/row
        split_kernel<<<(p + 255) / 256, 256>>>(x, U_XH, U_XL, p);
        p = 512 * 64;            // W0
        split_kernel<<<(p + 255) / 256, 256>>>(W0, U_W0H, U_W0L, p);
        p = 128 * 256;           // W1: 128 x 512 -> 256 pairs/row
        split_kernel<<<(p + 255) / 256, 256>>>(W1, U_W1H, U_W1L, p);
    }

    // ---- layer 0: H0 = x @ W0^T ----
    {
        dim3 grid(512 / TBN, (n + TBM - 1) / TBM);
        gemm_tc_kernel<<<grid, 256>>>(U_XH, U_XL, U_W0H, U_W0L, nullptr, B_H0, n, 512, 128);
    }
    attn_coef_kernel<<<n, 128>>>(B_H0, att_src0, att_dst0, B_EXT, B_AS0, B_AD0, 4);

    cudaStreamWaitEvent((cudaStream_t)0, evJoin, 0);
    agg0_kernel<<<n, 128>>>(b0);

    // ---- layer 1: H1 = H0A @ W1^T ----
    {
        dim3 grid(128 / TBN, (n + TBM - 1) / TBM);
        gemm_tc_kernel<<<grid, 256>>>(U_H0AH, U_H0AL, U_W1H, U_W1L, nullptr, B_H1, n, 128, 512);
    }
    attn_coef_kernel<<<n, 128>>>(B_H1, att_src1, att_dst1, B_EXT, B_AS1, B_AD1, 1);
    agg1_kernel<<<(n + 3) / 4, 128>>>(b1, n);

    // ---- edge scores directly from H1A: s1 = H1A.v1, s2 = H1A.v2 (Wout GEMM eliminated) ----
    attn_coef_kernel<<<n, 128>>>(B_H1A, nullptr, nullptr, B_V, B_S1, B_S2, 1);

    // ---- final n x n outer sum ----
    outer_kernel<<<n, 256>>>(bedge, out, n);
}

// round 9
// speedup vs baseline: 1.4246x; 1.4246x over previous
#include <cuda_runtime.h>
#include <cuda_bf16.h>
#include <math.h>

// ---------------- problem constants ----------------
#define NMAX 10000
#define EMAX 320000
#define MMAX (EMAX + NMAX)   // edges + self loops

// ---------------- device scratch ----------------
__device__ __align__(16) float g_H0 [NMAX * 512];
__device__ __align__(16) float g_H0A[NMAX * 512];
__device__ __align__(16) float g_H1 [NMAX * 128];
__device__ __align__(16) float g_H1A[NMAX * 128];
__device__ __align__(16) float g_AS0[NMAX * 4];
__device__ __align__(16) float g_AD0[NMAX * 4];
__device__ __align__(16) float g_AS1[NMAX];
__device__ __align__(16) float g_AD1[NMAX];
__device__ __align__(16) float g_S1 [NMAX];
__device__ __align__(16) float g_S2 [NMAX];
__device__ __align__(16) float g_V  [260];          // v1[128], v2[128], c
__device__ __align__(16) int   g_deg[NMAX];
__device__ __align__(16) int   g_off[NMAX + 1];
__device__ __align__(16) int   g_cur[NMAX];
__device__ __align__(16) int   g_srt[MMAX];

// buffer ids
#define B_H0   0
#define B_H0A  1
#define B_H1   2
#define B_H1A  3
#define B_AS0  5
#define B_AD0  6
#define B_AS1  7
#define B_AD1  8
#define B_S1   9
#define B_S2   10
#define B_V    11
#define B_EXT  (-1)

__device__ __forceinline__ float* buf_sel(int id) {
    switch (id) {
        case B_H0:  return g_H0;
        case B_H0A: return g_H0A;
        case B_H1:  return g_H1;
        case B_H1A: return g_H1A;
        case B_AS0: return g_AS0;
        case B_AD0: return g_AD0;
        case B_AS1: return g_AS1;
        case B_AD1: return g_AD1;
        case B_S1:  return g_S1;
        case B_V:   return g_V;
        default:    return g_S2;
    }
}

// ---------------- CSR build kernels ----------------
__global__ void zero_deg_kernel(int n) {
    int i = blockIdx.x * blockDim.x + threadIdx.x;
    if (i < n) g_deg[i] = 0;
}

__global__ void hist_kernel(const int* __restrict__ ei, int E, int n) {
    int e = blockIdx.x * blockDim.x + threadIdx.x;
    int M = E + n;
    if (e >= M) return;
    int dst = (e < E) ? ei[E + e] : (e - E);
    if ((unsigned)dst < (unsigned)n)
        atomicAdd(&g_deg[dst], 1);
}

__global__ void scan_kernel(int n) {
    __shared__ int sm[1024];
    int t = threadIdx.x;
    int chunk = (n + 1023) >> 10;
    int b = t * chunk;
    int e = min(n, b + chunk);
    int s = 0;
    for (int i = b; i < e; i++) s += g_deg[i];
    sm[t] = s;
    __syncthreads();
    for (int o = 1; o < 1024; o <<= 1) {
        int v = (t >= o) ? sm[t - o] : 0;
        __syncthreads();
        sm[t] += v;
        __syncthreads();
    }
    int run = sm[t] - s;
    for (int i = b; i < e; i++) {
        g_off[i] = run;
        g_cur[i] = run;
        run += g_deg[i];
    }
    if (t == 1023) g_off[n] = sm[1023];
}

__global__ void scatter_kernel(const int* __restrict__ ei, int E, int n) {
    int e = blockIdx.x * blockDim.x + threadIdx.x;
    int M = E + n;
    if (e >= M) return;
    int src, dst;
    if (e < E) { src = ei[e]; dst = ei[E + e]; }
    else       { src = e - E; dst = e - E; }
    if ((unsigned)dst >= (unsigned)n || (unsigned)src >= (unsigned)n) return;
    int pos = atomicAdd(&g_cur[dst], 1);
    if (pos < MMAX) g_srt[pos] = src;
}

// ---------------- v-vectors: v1 = Wout^T w1, v2 = Wout^T w2, c = bout.(w1+w2) ----------------
__global__ void vec_kernel(const float* __restrict__ Wout, const float* __restrict__ bout,
                           const float* __restrict__ Wedge) {
    int k = threadIdx.x;   // 128
    float a1 = 0.f, a2 = 0.f;
    for (int j = 0; j < 128; j++) {
        float wo = Wout[j * 128 + k];
        a1 += wo * Wedge[j];
        a2 += wo * Wedge[128 + j];
    }
    g_V[k] = a1;
    g_V[128 + k] = a2;
    if (k == 0) {
        float c = 0.f;
        for (int j = 0; j < 128; j++) c += bout[j] * (Wedge[j] + Wedge[128 + j]);
        g_V[256] = c;
    }
}

// ---------------- bf16x3 tensor-core GEMM: C[M,N] = A[M,K] * B[N,K]^T (+bias) ----------------
// Error-compensated: x = hi(bf16) + lo(bf16); C += Ahi*Bhi + Ahi*Blo + Alo*Bhi.
// Tile 128x64, TBK=32 (16 packed bf16x2 per row), 256 threads = 8 warps (2m x 4n).
// Row stride 20 uint32 -> fragment LDS is a perfect 32-bank permutation.
#define TBM 128
#define TBN 64
#define TBK 32
#define KP  (TBK / 2)     // 16 packed pairs
#define SSTR (KP + 4)     // 20

__device__ __forceinline__ unsigned pack_bf2(float a, float b) {
    __nv_bfloat162 p = __floats2bfloat162_rn(a, b);
    return *reinterpret_cast<unsigned*>(&p);
}

__device__ __forceinline__ void mma_bf16(float acc[4], unsigned a0, unsigned a1,
                                         unsigned a2, unsigned a3,
                                         unsigned b0, unsigned b1) {
    asm volatile(
        "mma.sync.aligned.m16n8k16.row.col.f32.bf16.bf16.f32 "
        "{%0,%1,%2,%3}, {%4,%5,%6,%7}, {%8,%9}, {%0,%1,%2,%3};"
        : "+f"(acc[0]), "+f"(acc[1]), "+f"(acc[2]), "+f"(acc[3])
        : "r"(a0), "r"(a1), "r"(a2), "r"(a3), "r"(b0), "r"(b1));
}

__global__ void __launch_bounds__(256)
gemm_tc_kernel(const float* __restrict__ Aext, int aid,
               const float* __restrict__ B,
               const float* __restrict__ bias,
               int cid, int M, int N, int K) {
    const float* A = (aid == B_EXT) ? Aext : buf_sel(aid);
    float* C = buf_sel(cid);

    __shared__ unsigned AsH[TBM * SSTR];
    __shared__ unsigned AsL[TBM * SSTR];
    __shared__ unsigned BsH[TBN * SSTR];
    __shared__ unsigned BsL[TBN * SSTR];

    int tid = threadIdx.x;
    int warp = tid >> 5, lane = tid & 31;
    int wm = warp >> 2;          // 0..1
    int wn = warp & 3;           // 0..3
    int bm = blockIdx.y * TBM;
    int bn = blockIdx.x * TBN;

    int lr = tid >> 3;           // 0..31 (load row)
    int lc = tid & 7;            // 0..7  (4 floats = 2 packed pairs)

    float acc[4][2][4];
#pragma unroll
    for (int mt = 0; mt < 4; mt++)
#pragma unroll
        for (int nt = 0; nt < 2; nt++)
#pragma unroll
            for (int r = 0; r < 4; r++) acc[mt][nt][r] = 0.f;

    int qrow = lane >> 2;        // 0..7
    int qcol = lane & 3;         // 0..3

    for (int k0 = 0; k0 < K; k0 += TBK) {
        // load + split A tile: 128 rows x 32 k
#pragma unroll
        for (int i = 0; i < 4; i++) {
            int rl = lr + 32 * i;
            int rg = bm + rl;
            float4 v = {0.f, 0.f, 0.f, 0.f};
            if (rg < M) v = *(const float4*)&A[(size_t)rg * K + k0 + lc * 4];
            float hx = __bfloat162float(__float2bfloat16_rn(v.x));
            float hy = __bfloat162float(__float2bfloat16_rn(v.y));
            float hz = __bfloat162float(__float2bfloat16_rn(v.z));
            float hw = __bfloat162float(__float2bfloat16_rn(v.w));
            unsigned* dH = &AsH[rl * SSTR + lc * 2];
            unsigned* dL = &AsL[rl * SSTR + lc * 2];
            dH[0] = pack_bf2(hx, hy);
            dH[1] = pack_bf2(hz, hw);
            dL[0] = pack_bf2(v.x - hx, v.y - hy);
            dL[1] = pack_bf2(v.z - hz, v.w - hw);
        }
        // load + split B tile: 64 rows x 32 k (N multiple of 64 -> no guard)
#pragma unroll
        for (int i = 0; i < 2; i++) {
            int rl = lr + 32 * i;
            float4 v = *(const float4*)&B[(size_t)(bn + rl) * K + k0 + lc * 4];
            float hx = __bfloat162float(__float2bfloat16_rn(v.x));
            float hy = __bfloat162float(__float2bfloat16_rn(v.y));
            float hz = __bfloat162float(__float2bfloat16_rn(v.z));
            float hw = __bfloat162float(__float2bfloat16_rn(v.w));
            unsigned* dH = &BsH[rl * SSTR + lc * 2];
            unsigned* dL = &BsL[rl * SSTR + lc * 2];
            dH[0] = pack_bf2(hx, hy);
            dH[1] = pack_bf2(hz, hw);
            dL[0] = pack_bf2(v.x - hx, v.y - hy);
            dL[1] = pack_bf2(v.z - hz, v.w - hw);
        }
        __syncthreads();

#pragma unroll
        for (int ks = 0; ks < TBK / 16; ks++) {
            int kb = ks * 8;     // packed-pair offset of this k16 slab
            unsigned bh[2][2], bl[2][2];
#pragma unroll
            for (int nt = 0; nt < 2; nt++) {
                int nn = wn * 16 + nt * 8 + qrow;
                bh[nt][0] = BsH[nn * SSTR + kb + qcol];
                bh[nt][1] = BsH[nn * SSTR + kb + qcol + 4];
                bl[nt][0] = BsL[nn * SSTR + kb + qcol];
                bl[nt][1] = BsL[nn * SSTR + kb + qcol + 4];
            }
#pragma unroll
            for (int mt = 0; mt < 4; mt++) {
                int mm = wm * 64 + mt * 16 + qrow;
                unsigned ah0 = AsH[mm * SSTR + kb + qcol];
                unsigned ah1 = AsH[(mm + 8) * SSTR + kb + qcol];
                unsigned ah2 = AsH[mm * SSTR + kb + qcol + 4];
                unsigned ah3 = AsH[(mm + 8) * SSTR + kb + qcol + 4];
                unsigned al0 = AsL[mm * SSTR + kb + qcol];
                unsigned al1 = AsL[(mm + 8) * SSTR + kb + qcol];
                unsigned al2 = AsL[mm * SSTR + kb + qcol + 4];
                unsigned al3 = AsL[(mm + 8) * SSTR + kb + qcol + 4];
#pragma unroll
                for (int nt = 0; nt < 2; nt++) {
                    mma_bf16(acc[mt][nt], ah0, ah1, ah2, ah3, bh[nt][0], bh[nt][1]);
                    mma_bf16(acc[mt][nt], ah0, ah1, ah2, ah3, bl[nt][0], bl[nt][1]);
                    mma_bf16(acc[mt][nt], al0, al1, al2, al3, bh[nt][0], bh[nt][1]);
                }
            }
        }
        __syncthreads();
    }

    // epilogue
#pragma unroll
    for (int mt = 0; mt < 4; mt++) {
#pragma unroll
        for (int nt = 0; nt < 2; nt++) {
            int row = bm + wm * 64 + mt * 16 + qrow;
            int col = bn + wn * 16 + nt * 8 + qcol * 2;
            float b0 = 0.f, b1 = 0.f;
            if (bias) { b0 = bias[col]; b1 = bias[col + 1]; }
            if (row < M) {
                float2 o = {acc[mt][nt][0] + b0, acc[mt][nt][1] + b1};
                *(float2*)&C[(size_t)row * N + col] = o;
            }
            if (row + 8 < M) {
                float2 o = {acc[mt][nt][2] + b0, acc[mt][nt][3] + b1};
                *(float2*)&C[(size_t)(row + 8) * N + col] = o;
            }
        }
    }
}

// ---------------- attention coefficients: out[n,h] = sum_c H[n,h,c]*att[h,c] ----------------
__global__ void attn_coef_kernel(int hid, const float* __restrict__ atts_ext,
                                 const float* __restrict__ attd_ext,
                                 int attid,       // if >= 0: atts = buf_sel(attid), attd = atts+128
                                 int osid, int odid, int heads) {
    const float* H = buf_sel(hid);
    const float* atts = (attid >= 0) ? buf_sel(attid) : atts_ext;
    const float* attd = (attid >= 0) ? buf_sel(attid) + 128 : attd_ext;
    float* osrc = buf_sel(osid);
    float* odst = buf_sel(odid);

    int node = blockIdx.x;
    int t = threadIdx.x;            // 128
    int w = t >> 5, lane = t & 31;
    int Ct = heads * 128;
    float ps[4] = {0.f, 0.f, 0.f, 0.f}, pd[4] = {0.f, 0.f, 0.f, 0.f};
    for (int k = 0; k < heads; k++) {
        float h = H[(size_t)node * Ct + k * 128 + t];
        ps[k] = h * atts[k * 128 + t];
        pd[k] = h * attd[k * 128 + t];
    }
#pragma unroll
    for (int o = 16; o; o >>= 1) {
#pragma unroll
        for (int k = 0; k < 4; k++) {
            ps[k] += __shfl_xor_sync(~0u, ps[k], o);
            pd[k] += __shfl_xor_sync(~0u, pd[k], o);
        }
    }
    __shared__ float ss[4][4], sd[4][4];
    if (lane == 0) {
#pragma unroll
        for (int k = 0; k < 4; k++) { ss[w][k] = ps[k]; sd[w][k] = pd[k]; }
    }
    __syncthreads();
    if (t < heads) {
        osrc[node * heads + t] = ss[0][t] + ss[1][t] + ss[2][t] + ss[3][t];
        odst[node * heads + t] = sd[0][t] + sd[1][t] + sd[2][t] + sd[3][t];
    }
}

// ---------------- layer-0 aggregation (single pass, no max) ----------------
__global__ void agg0_kernel(const float* __restrict__ b0) {
    int node = blockIdx.x;
    int t = threadIdx.x;            // 128
    int w = t >> 5;
    int beg = g_off[node], end = g_off[node + 1];

    float adsth = g_AD0[node * 4 + w];

    float4 acc = {0.f, 0.f, 0.f, 0.f};
    float denom = 0.f;
    for (int i = beg; i < end; i++) {
        int s = g_srt[i];
        float a = g_AS0[s * 4 + w] + adsth;
        a = (a >= 0.f) ? a : 0.2f * a;
        float ex = __expf(a);
        denom += ex;
        float4 v = *(const float4*)&g_H0[(size_t)s * 512 + t * 4];
        acc.x += ex * v.x; acc.y += ex * v.y; acc.z += ex * v.z; acc.w += ex * v.w;
    }
    float inv = 1.f / (denom + 1e-16f);
    float4 bb = *(const float4*)&b0[t * 4];
    float4 o4;
    o4.x = acc.x * inv + bb.x;
    o4.y = acc.y * inv + bb.y;
    o4.z = acc.z * inv + bb.z;
    o4.w = acc.w * inv + bb.w;
    o4.x = (o4.x > 0.f) ? o4.x : expm1f(o4.x);
    o4.y = (o4.y > 0.f) ? o4.y : expm1f(o4.y);
    o4.z = (o4.z > 0.f) ? o4.z : expm1f(o4.z);
    o4.w = (o4.w > 0.f) ? o4.w : expm1f(o4.w);
    *(float4*)&g_H0A[(size_t)node * 512 + t * 4] = o4;
}

// ---------------- layer-1 aggregation (single pass, no max) ----------------
__global__ void agg1_kernel(const float* __restrict__ b1, int n) {
    int w = threadIdx.x >> 5, lane = threadIdx.x & 31;
    int node = blockIdx.x * 4 + w;
    if (node >= n) return;
    int beg = g_off[node], end = g_off[node + 1];
    float adv = g_AD1[node];

    float4 acc = {0.f, 0.f, 0.f, 0.f};
    float denom = 0.f;
    for (int i = beg; i < end; i++) {
        int s = g_srt[i];
        float a = g_AS1[s] + adv;
        a = (a >= 0.f) ? a : 0.2f * a;
        float ex = __expf(a);
        denom += ex;
        float4 v = *(const float4*)&g_H1[(size_t)s * 128 + lane * 4];
        acc.x += ex * v.x; acc.y += ex * v.y; acc.z += ex * v.z; acc.w += ex * v.w;
    }
    float inv = 1.f / (denom + 1e-16f);
    float4 bb = *(const float4*)&b1[lane * 4];
    float4 o4;
    o4.x = acc.x * inv + bb.x;
    o4.y = acc.y * inv + bb.y;
    o4.z = acc.z * inv + bb.z;
    o4.w = acc.w * inv + bb.w;
    o4.x = (o4.x > 0.f) ? o4.x : expm1f(o4.x);
    o4.y = (o4.y > 0.f) ? o4.y : expm1f(o4.y);
    o4.z = (o4.z > 0.f) ? o4.z : expm1f(o4.z);
    o4.w = (o4.w > 0.f) ? o4.w : expm1f(o4.w);
    *(float4*)&g_H1A[(size_t)node * 128 + lane * 4] = o4;
}

// ---------------- final outer sum: out[i*n+j] = s1[i] + s2[j] + c + bedge ----------------
__global__ void outer_kernel(const float* __restrict__ bedge, float* __restrict__ out, int n) {
    int i = blockIdx.x;
    float v = g_S1[i] + bedge[0] + g_V[256];
    float* row = out + (size_t)i * n;
    int n4 = n >> 2;
    const float4* s24 = (const float4*)g_S2;
    for (int j = threadIdx.x; j < n4; j += blockDim.x) {
        float4 b = s24[j];
        float4 o = {v + b.x, v + b.y, v + b.z, v + b.w};
        ((float4*)row)[j] = o;
    }
    for (int j = (n4 << 2) + threadIdx.x; j < n; j += blockDim.x)
        row[j] = v + g_S2[j];
}

// ---------------- host launcher ----------------
extern "C" void kernel_launch(void* const* d_in, const int* in_sizes, int n_in,
                              void* d_out, int out_size) {
    const float* x        = (const float*)d_in[0];
    const int*   ei       = (const int*)d_in[1];     // int32
    const float* W0       = (const float*)d_in[2];
    const float* att_src0 = (const float*)d_in[3];
    const float* att_dst0 = (const float*)d_in[4];
    const float* b0       = (const float*)d_in[5];
    const float* W1       = (const float*)d_in[6];
    const float* att_src1 = (const float*)d_in[7];
    const float* att_dst1 = (const float*)d_in[8];
    const float* b1       = (const float*)d_in[9];
    const float* Wout     = (const float*)d_in[10];
    const float* bout     = (const float*)d_in[11];
    const float* Wedge    = (const float*)d_in[12];
    const float* bedge    = (const float*)d_in[13];
    float* out = (float*)d_out;

    int n = in_sizes[0] / 128;
    int E = in_sizes[1] / 2;
    int M = E + n;

    // Fork side stream: CSR build + v-vector kernel overlap GEMM0+attn0.
    cudaStream_t side;
    cudaStreamCreateWithFlags(&side, cudaStreamNonBlocking);
    cudaEvent_t evFork, evJoin;
    cudaEventCreateWithFlags(&evFork, cudaEventDisableTiming);
    cudaEventCreateWithFlags(&evJoin, cudaEventDisableTiming);

    cudaEventRecord(evFork, (cudaStream_t)0);
    cudaStreamWaitEvent(side, evFork, 0);

    zero_deg_kernel<<<(n + 255) / 256, 256, 0, side>>>(n);
    hist_kernel<<<(M + 255) / 256, 256, 0, side>>>(ei, E, n);
    scan_kernel<<<1, 1024, 0, side>>>(n);
    scatter_kernel<<<(M + 255) / 256, 256, 0, side>>>(ei, E, n);
    vec_kernel<<<1, 128, 0, side>>>(Wout, bout, Wedge);
    cudaEventRecord(evJoin, side);

    // ---- layer 0: H0 = x @ W0^T (bf16x3 TC, in-kernel split) ----
    {
        dim3 grid(512 / TBN, (n + TBM - 1) / TBM);
        gemm_tc_kernel<<<grid, 256>>>(x, B_EXT, W0, nullptr, B_H0, n, 512, 128);
    }
    attn_coef_kernel<<<n, 128>>>(B_H0, att_src0, att_dst0, B_EXT, B_AS0, B_AD0, 4);

    cudaStreamWaitEvent((cudaStream_t)0, evJoin, 0);
    agg0_kernel<<<n, 128>>>(b0);

    // ---- layer 1: H1 = H0A @ W1^T ----
    {
        dim3 grid(128 / TBN, (n + TBM - 1) / TBM);
        gemm_tc_kernel<<<grid, 256>>>(nullptr, B_H0A, W1, nullptr, B_H1, n, 128, 512);
    }
    attn_coef_kernel<<<n, 128>>>(B_H1, att_src1, att_dst1, B_EXT, B_AS1, B_AD1, 1);
    agg1_kernel<<<(n + 3) / 4, 128>>>(b1, n);

    // ---- edge scores directly from H1A: s1 = H1A.v1, s2 = H1A.v2 (Wout GEMM eliminated) ----
    attn_coef_kernel<<<n, 128>>>(B_H1A, nullptr, nullptr, B_V, B_S1, B_S2, 1);

    // ---- final n x n outer sum ----
    outer_kernel<<<n, 256>>>(bedge, out, n);
}

// round 10
// speedup vs baseline: 1.4256x; 1.0007x over previous
#include <cuda_runtime.h>
#include <cuda_bf16.h>
#include <math.h>

// ---------------- problem constants ----------------
#define NMAX 10000
#define EMAX 320000
#define MMAX (EMAX + NMAX)   // edges + self loops

// ---------------- device scratch ----------------
__device__ __align__(16) float g_H0 [NMAX * 512];
__device__ __align__(16) float g_H0A[NMAX * 512];
__device__ __align__(16) float g_H1 [NMAX * 128];
__device__ __align__(16) float g_H1A[NMAX * 128];
__device__ __align__(16) float g_AS0[NMAX * 4];
__device__ __align__(16) float g_AD0[NMAX * 4];
__device__ __align__(16) float g_AS1[NMAX];
__device__ __align__(16) float g_AD1[NMAX];
__device__ __align__(16) float g_S1 [NMAX];
__device__ __align__(16) float g_S2 [NMAX];
__device__ __align__(16) float g_V  [260];          // v1[128], v2[128], c
__device__ __align__(16) int   g_deg[NMAX];
__device__ __align__(16) int   g_off[NMAX + 1];
__device__ __align__(16) int   g_cur[NMAX];
__device__ __align__(16) int   g_srt[MMAX];

// buffer ids
#define B_H0   0
#define B_H0A  1
#define B_H1   2
#define B_H1A  3
#define B_AS0  5
#define B_AD0  6
#define B_AS1  7
#define B_AD1  8
#define B_S1   9
#define B_S2   10
#define B_V    11
#define B_EXT  (-1)

__device__ __forceinline__ float* buf_sel(int id) {
    switch (id) {
        case B_H0:  return g_H0;
        case B_H0A: return g_H0A;
        case B_H1:  return g_H1;
        case B_H1A: return g_H1A;
        case B_AS0: return g_AS0;
        case B_AD0: return g_AD0;
        case B_AS1: return g_AS1;
        case B_AD1: return g_AD1;
        case B_S1:  return g_S1;
        case B_V:   return g_V;
        default:    return g_S2;
    }
}

// ---------------- CSR build kernels ----------------
__global__ void zero_deg_kernel(int n) {
    int i = blockIdx.x * blockDim.x + threadIdx.x;
    if (i < n) g_deg[i] = 0;
}

__global__ void hist_kernel(const int* __restrict__ ei, int E, int n) {
    int e = blockIdx.x * blockDim.x + threadIdx.x;
    int M = E + n;
    if (e >= M) return;
    int dst = (e < E) ? ei[E + e] : (e - E);
    if ((unsigned)dst < (unsigned)n)
        atomicAdd(&g_deg[dst], 1);
}

__global__ void scan_kernel(int n) {
    __shared__ int sm[1024];
    int t = threadIdx.x;
    int chunk = (n + 1023) >> 10;
    int b = t * chunk;
    int e = min(n, b + chunk);
    int s = 0;
    for (int i = b; i < e; i++) s += g_deg[i];
    sm[t] = s;
    __syncthreads();
    for (int o = 1; o < 1024; o <<= 1) {
        int v = (t >= o) ? sm[t - o] : 0;
        __syncthreads();
        sm[t] += v;
        __syncthreads();
    }
    int run = sm[t] - s;
    for (int i = b; i < e; i++) {
        g_off[i] = run;
        g_cur[i] = run;
        run += g_deg[i];
    }
    if (t == 1023) g_off[n] = sm[1023];
}

__global__ void scatter_kernel(const int* __restrict__ ei, int E, int n) {
    int e = blockIdx.x * blockDim.x + threadIdx.x;
    int M = E + n;
    if (e >= M) return;
    int src, dst;
    if (e < E) { src = ei[e]; dst = ei[E + e]; }
    else       { src = e - E; dst = e - E; }
    if ((unsigned)dst >= (unsigned)n || (unsigned)src >= (unsigned)n) return;
    int pos = atomicAdd(&g_cur[dst], 1);
    if (pos < MMAX) g_srt[pos] = src;
}

// ---------------- v-vectors: v1 = Wout^T w1, v2 = Wout^T w2, c = bout.(w1+w2) ----------------
__global__ void vec_kernel(const float* __restrict__ Wout, const float* __restrict__ bout,
                           const float* __restrict__ Wedge) {
    int k = threadIdx.x;   // 128
    float a1 = 0.f, a2 = 0.f;
    for (int j = 0; j < 128; j++) {
        float wo = Wout[j * 128 + k];
        a1 += wo * Wedge[j];
        a2 += wo * Wedge[128 + j];
    }
    g_V[k] = a1;
    g_V[128 + k] = a2;
    if (k == 0) {
        float c = 0.f;
        for (int j = 0; j < 128; j++) c += bout[j] * (Wedge[j] + Wedge[128 + j]);
        g_V[256] = c;
    }
}

// ---------------- bf16x3 TC GEMM, software-pipelined double buffer ----------------
// C[M,N] = A[M,K] * B[N,K]^T (+bias); C += Ahi*Bhi + Ahi*Blo + Alo*Bhi.
// Tile 128x64, TBK=32, 256 thr = 8 warps (2m x 4n).
// Row stride 20 uint32 -> fragment LDS is a perfect 32-bank permutation.
// Dynamic smem: 2 buffers x (A hi/lo + B hi/lo) = 61440 bytes.
#define TBM 128
#define TBN 64
#define TBK 32
#define KP  (TBK / 2)     // 16 packed pairs
#define SSTR (KP + 4)     // 20
#define A_SZ (TBM * SSTR) // 2560 uints
#define B_SZ (TBN * SSTR) // 1280 uints
#define GSMEM_BYTES (2 * (A_SZ + A_SZ + B_SZ + B_SZ) * 4)  // 61440

__device__ __forceinline__ unsigned pack_bf2(float a, float b) {
    __nv_bfloat162 p = __floats2bfloat162_rn(a, b);
    return *reinterpret_cast<unsigned*>(&p);
}

__device__ __forceinline__ void mma_bf16(float acc[4], unsigned a0, unsigned a1,
                                         unsigned a2, unsigned a3,
                                         unsigned b0, unsigned b1) {
    asm volatile(
        "mma.sync.aligned.m16n8k16.row.col.f32.bf16.bf16.f32 "
        "{%0,%1,%2,%3}, {%4,%5,%6,%7}, {%8,%9}, {%0,%1,%2,%3};"
        : "+f"(acc[0]), "+f"(acc[1]), "+f"(acc[2]), "+f"(acc[3])
        : "r"(a0), "r"(a1), "r"(a2), "r"(a3), "r"(b0), "r"(b1));
}

__global__ void __launch_bounds__(256)
gemm_tc_kernel(const float* __restrict__ Aext, int aid,
               const float* __restrict__ B,
               const float* __restrict__ bias,
               int cid, int M, int N, int K) {
    const float* A = (aid == B_EXT) ? Aext : buf_sel(aid);
    float* C = buf_sel(cid);

    extern __shared__ unsigned smu[];
    unsigned* AsH = smu;                     // [2][A_SZ]
    unsigned* AsL = AsH + 2 * A_SZ;          // [2][A_SZ]
    unsigned* BsH = AsL + 2 * A_SZ;          // [2][B_SZ]
    unsigned* BsL = BsH + 2 * B_SZ;          // [2][B_SZ]

    int tid = threadIdx.x;
    int warp = tid >> 5, lane = tid & 31;
    int wm = warp >> 2;          // 0..1
    int wn = warp & 3;           // 0..3
    int bm = blockIdx.y * TBM;
    int bn = blockIdx.x * TBN;

    int lr = tid >> 3;           // 0..31 (load row)
    int lc = tid & 7;            // 0..7  (4 floats = 2 packed pairs)

    float acc[4][2][4];
#pragma unroll
    for (int mt = 0; mt < 4; mt++)
#pragma unroll
        for (int nt = 0; nt < 2; nt++)
#pragma unroll
            for (int r = 0; r < 4; r++) acc[mt][nt][r] = 0.f;

    int qrow = lane >> 2;        // 0..7
    int qcol = lane & 3;         // 0..3

    float4 ra[4], rb[2];

    auto load_tile = [&](int k0) {
#pragma unroll
        for (int i = 0; i < 4; i++) {
            int rg = bm + lr + 32 * i;
            ra[i] = make_float4(0.f, 0.f, 0.f, 0.f);
            if (rg < M) ra[i] = *(const float4*)&A[(size_t)rg * K + k0 + lc * 4];
        }
#pragma unroll
        for (int i = 0; i < 2; i++)
            rb[i] = *(const float4*)&B[(size_t)(bn + lr + 32 * i) * K + k0 + lc * 4];
    };

    auto cvt_store = [&](int buf) {
        unsigned* aH = AsH + buf * A_SZ;
        unsigned* aL = AsL + buf * A_SZ;
        unsigned* bH = BsH + buf * B_SZ;
        unsigned* bL = BsL + buf * B_SZ;
#pragma unroll
        for (int i = 0; i < 4; i++) {
            float4 v = ra[i];
            float hx = __bfloat162float(__float2bfloat16_rn(v.x));
            float hy = __bfloat162float(__float2bfloat16_rn(v.y));
            float hz = __bfloat162float(__float2bfloat16_rn(v.z));
            float hw = __bfloat162float(__float2bfloat16_rn(v.w));
            int rl = lr + 32 * i;
            unsigned* dH = &aH[rl * SSTR + lc * 2];
            unsigned* dL = &aL[rl * SSTR + lc * 2];
            dH[0] = pack_bf2(hx, hy);
            dH[1] = pack_bf2(hz, hw);
            dL[0] = pack_bf2(v.x - hx, v.y - hy);
            dL[1] = pack_bf2(v.z - hz, v.w - hw);
        }
#pragma unroll
        for (int i = 0; i < 2; i++) {
            float4 v = rb[i];
            float hx = __bfloat162float(__float2bfloat16_rn(v.x));
            float hy = __bfloat162float(__float2bfloat16_rn(v.y));
            float hz = __bfloat162float(__float2bfloat16_rn(v.z));
            float hw = __bfloat162float(__float2bfloat16_rn(v.w));
            int rl = lr + 32 * i;
            unsigned* dH = &bH[rl * SSTR + lc * 2];
            unsigned* dL = &bL[rl * SSTR + lc * 2];
            dH[0] = pack_bf2(hx, hy);
            dH[1] = pack_bf2(hz, hw);
            dL[0] = pack_bf2(v.x - hx, v.y - hy);
            dL[1] = pack_bf2(v.z - hz, v.w - hw);
        }
    };

    int nTiles = K / TBK;

    // prologue: tile 0 -> buffer 0
    load_tile(0);
    cvt_store(0);
    __syncthreads();

    for (int kt = 0; kt < nTiles; kt++) {
        int cur = kt & 1;
        // prefetch next tile into registers (LDGs overlap the MMAs below)
        if (kt + 1 < nTiles) load_tile((kt + 1) * TBK);

        unsigned* aH = AsH + cur * A_SZ;
        unsigned* aL = AsL + cur * A_SZ;
        unsigned* bH = BsH + cur * B_SZ;
        unsigned* bL = BsL + cur * B_SZ;

#pragma unroll
        for (int ks = 0; ks < TBK / 16; ks++) {
            int kb = ks * 8;     // packed-pair offset of this k16 slab
            unsigned bh[2][2], bl[2][2];
#pragma unroll
            for (int nt = 0; nt < 2; nt++) {
                int nn = wn * 16 + nt * 8 + qrow;
                bh[nt][0] = bH[nn * SSTR + kb + qcol];
                bh[nt][1] = bH[nn * SSTR + kb + qcol + 4];
                bl[nt][0] = bL[nn * SSTR + kb + qcol];
                bl[nt][1] = bL[nn * SSTR + kb + qcol + 4];
            }
#pragma unroll
            for (int mt = 0; mt < 4; mt++) {
                int mm = wm * 64 + mt * 16 + qrow;
                unsigned ah0 = aH[mm * SSTR + kb + qcol];
                unsigned ah1 = aH[(mm + 8) * SSTR + kb + qcol];
                unsigned ah2 = aH[mm * SSTR + kb + qcol + 4];
                unsigned ah3 = aH[(mm + 8) * SSTR + kb + qcol + 4];
                unsigned al0 = aL[mm * SSTR + kb + qcol];
                unsigned al1 = aL[(mm + 8) * SSTR + kb + qcol];
                unsigned al2 = aL[mm * SSTR + kb + qcol + 4];
                unsigned al3 = aL[(mm + 8) * SSTR + kb + qcol + 4];
#pragma unroll
                for (int nt = 0; nt < 2; nt++) {
                    mma_bf16(acc[mt][nt], ah0, ah1, ah2, ah3, bh[nt][0], bh[nt][1]);
                    mma_bf16(acc[mt][nt], ah0, ah1, ah2, ah3, bl[nt][0], bl[nt][1]);
                    mma_bf16(acc[mt][nt], al0, al1, al2, al3, bh[nt][0], bh[nt][1]);
                }
            }
        }

        // convert + store next tile into the other buffer, then one barrier
        if (kt + 1 < nTiles) cvt_store((kt + 1) & 1);
        __syncthreads();
    }

    // epilogue
#pragma unroll
    for (int mt = 0; mt < 4; mt++) {
#pragma unroll
        for (int nt = 0; nt < 2; nt++) {
            int row = bm + wm * 64 + mt * 16 + qrow;
            int col = bn + wn * 16 + nt * 8 + qcol * 2;
            float b0 = 0.f, b1 = 0.f;
            if (bias) { b0 = bias[col]; b1 = bias[col + 1]; }
            if (row < M) {
                float2 o = {acc[mt][nt][0] + b0, acc[mt][nt][1] + b1};
                *(float2*)&C[(size_t)row * N + col] = o;
            }
            if (row + 8 < M) {
                float2 o = {acc[mt][nt][2] + b0, acc[mt][nt][3] + b1};
                *(float2*)&C[(size_t)(row + 8) * N + col] = o;
            }
        }
    }
}

// ---------------- attention coefficients: out[n,h] = sum_c H[n,h,c]*att[h,c] ----------------
__global__ void attn_coef_kernel(int hid, const float* __restrict__ atts_ext,
                                 const float* __restrict__ attd_ext,
                                 int attid,       // if >= 0: atts = buf_sel(attid), attd = atts+128
                                 int osid, int odid, int heads) {
    const float* H = buf_sel(hid);
    const float* atts = (attid >= 0) ? buf_sel(attid) : atts_ext;
    const float* attd = (attid >= 0) ? buf_sel(attid) + 128 : attd_ext;
    float* osrc = buf_sel(osid);
    float* odst = buf_sel(odid);

    int node = blockIdx.x;
    int t = threadIdx.x;            // 128
    int w = t >> 5, lane = t & 31;
    int Ct = heads * 128;
    float ps[4] = {0.f, 0.f, 0.f, 0.f}, pd[4] = {0.f, 0.f, 0.f, 0.f};
    for (int k = 0; k < heads; k++) {
        float h = H[(size_t)node * Ct + k * 128 + t];
        ps[k] = h * atts[k * 128 + t];
        pd[k] = h * attd[k * 128 + t];
    }
#pragma unroll
    for (int o = 16; o; o >>= 1) {
#pragma unroll
        for (int k = 0; k < 4; k++) {
            ps[k] += __shfl_xor_sync(~0u, ps[k], o);
            pd[k] += __shfl_xor_sync(~0u, pd[k], o);
        }
    }
    __shared__ float ss[4][4], sd[4][4];
    if (lane == 0) {
#pragma unroll
        for (int k = 0; k < 4; k++) { ss[w][k] = ps[k]; sd[w][k] = pd[k]; }
    }
    __syncthreads();
    if (t < heads) {
        osrc[node * heads + t] = ss[0][t] + ss[1][t] + ss[2][t] + ss[3][t];
        odst[node * heads + t] = sd[0][t] + sd[1][t] + sd[2][t] + sd[3][t];
    }
}

// ---------------- layer-0 aggregation (single pass, no max) ----------------
__global__ void agg0_kernel(const float* __restrict__ b0) {
    int node = blockIdx.x;
    int t = threadIdx.x;            // 128
    int w = t >> 5;
    int beg = g_off[node], end = g_off[node + 1];

    float adsth = g_AD0[node * 4 + w];

    float4 acc = {0.f, 0.f, 0.f, 0.f};
    float denom = 0.f;
    for (int i = beg; i < end; i++) {
        int s = g_srt[i];
        float a = g_AS0[s * 4 + w] + adsth;
        a = (a >= 0.f) ? a : 0.2f * a;
        float ex = __expf(a);
        denom += ex;
        float4 v = *(const float4*)&g_H0[(size_t)s * 512 + t * 4];
        acc.x += ex * v.x; acc.y += ex * v.y; acc.z += ex * v.z; acc.w += ex * v.w;
    }
    float inv = 1.f / (denom + 1e-16f);
    float4 bb = *(const float4*)&b0[t * 4];
    float4 o4;
    o4.x = acc.x * inv + bb.x;
    o4.y = acc.y * inv + bb.y;
    o4.z = acc.z * inv + bb.z;
    o4.w = acc.w * inv + bb.w;
    o4.x = (o4.x > 0.f) ? o4.x : expm1f(o4.x);
    o4.y = (o4.y > 0.f) ? o4.y : expm1f(o4.y);
    o4.z = (o4.z > 0.f) ? o4.z : expm1f(o4.z);
    o4.w = (o4.w > 0.f) ? o4.w : expm1f(o4.w);
    *(float4*)&g_H0A[(size_t)node * 512 + t * 4] = o4;
}

// ---------------- layer-1 aggregation (single pass, no max) ----------------
__global__ void agg1_kernel(const float* __restrict__ b1, int n) {
    int w = threadIdx.x >> 5, lane = threadIdx.x & 31;
    int node = blockIdx.x * 4 + w;
    if (node >= n) return;
    int beg = g_off[node], end = g_off[node + 1];
    float adv = g_AD1[node];

    float4 acc = {0.f, 0.f, 0.f, 0.f};
    float denom = 0.f;
    for (int i = beg; i < end; i++) {
        int s = g_srt[i];
        float a = g_AS1[s] + adv;
        a = (a >= 0.f) ? a : 0.2f * a;
        float ex = __expf(a);
        denom += ex;
        float4 v = *(const float4*)&g_H1[(size_t)s * 128 + lane * 4];
        acc.x += ex * v.x; acc.y += ex * v.y; acc.z += ex * v.z; acc.w += ex * v.w;
    }
    float inv = 1.f / (denom + 1e-16f);
    float4 bb = *(const float4*)&b1[lane * 4];
    float4 o4;
    o4.x = acc.x * inv + bb.x;
    o4.y = acc.y * inv + bb.y;
    o4.z = acc.z * inv + bb.z;
    o4.w = acc.w * inv + bb.w;
    o4.x = (o4.x > 0.f) ? o4.x : expm1f(o4.x);
    o4.y = (o4.y > 0.f) ? o4.y : expm1f(o4.y);
    o4.z = (o4.z > 0.f) ? o4.z : expm1f(o4.z);
    o4.w = (o4.w > 0.f) ? o4.w : expm1f(o4.w);
    *(float4*)&g_H1A[(size_t)node * 128 + lane * 4] = o4;
}

// ---------------- final outer sum: out[i*n+j] = s1[i] + s2[j] + c + bedge ----------------
__global__ void outer_kernel(const float* __restrict__ bedge, float* __restrict__ out, int n) {
    int i = blockIdx.x;
    float v = g_S1[i] + bedge[0] + g_V[256];
    float* row = out + (size_t)i * n;
    int n4 = n >> 2;
    const float4* s24 = (const float4*)g_S2;
    for (int j = threadIdx.x; j < n4; j += blockDim.x) {
        float4 b = s24[j];
        float4 o = {v + b.x, v + b.y, v + b.z, v + b.w};
        ((float4*)row)[j] = o;
    }
    for (int j = (n4 << 2) + threadIdx.x; j < n; j += blockDim.x)
        row[j] = v + g_S2[j];
}

// ---------------- host launcher ----------------
extern "C" void kernel_launch(void* const* d_in, const int* in_sizes, int n_in,
                              void* d_out, int out_size) {
    const float* x        = (const float*)d_in[0];
    const int*   ei       = (const int*)d_in[1];     // int32
    const float* W0       = (const float*)d_in[2];
    const float* att_src0 = (const float*)d_in[3];
    const float* att_dst0 = (const float*)d_in[4];
    const float* b0       = (const float*)d_in[5];
    const float* W1       = (const float*)d_in[6];
    const float* att_src1 = (const float*)d_in[7];
    const float* att_dst1 = (const float*)d_in[8];
    const float* b1       = (const float*)d_in[9];
    const float* Wout     = (const float*)d_in[10];
    const float* bout     = (const float*)d_in[11];
    const float* Wedge    = (const float*)d_in[12];
    const float* bedge    = (const float*)d_in[13];
    float* out = (float*)d_out;

    int n = in_sizes[0] / 128;
    int E = in_sizes[1] / 2;
    int M = E + n;

    // allow 60KB dynamic smem on the GEMM (host-side attribute; no device alloc)
    cudaFuncSetAttribute(gemm_tc_kernel,
                         cudaFuncAttributeMaxDynamicSharedMemorySize, GSMEM_BYTES);

    // Fork side stream: CSR build + v-vector kernel overlap GEMM0+attn0.
    cudaStream_t side;
    cudaStreamCreateWithFlags(&side, cudaStreamNonBlocking);
    cudaEvent_t evFork, evJoin;
    cudaEventCreateWithFlags(&evFork, cudaEventDisableTiming);
    cudaEventCreateWithFlags(&evJoin, cudaEventDisableTiming);

    cudaEventRecord(evFork, (cudaStream_t)0);
    cudaStreamWaitEvent(side, evFork, 0);

    zero_deg_kernel<<<(n + 255) / 256, 256, 0, side>>>(n);
    hist_kernel<<<(M + 255) / 256, 256, 0, side>>>(ei, E, n);
    scan_kernel<<<1, 1024, 0, side>>>(n);
    scatter_kernel<<<(M + 255) / 256, 256, 0, side>>>(ei, E, n);
    vec_kernel<<<1, 128, 0, side>>>(Wout, bout, Wedge);
    cudaEventRecord(evJoin, side);

    // ---- layer 0: H0 = x @ W0^T (bf16x3 TC, pipelined) ----
    {
        dim3 grid(512 / TBN, (n + TBM - 1) / TBM);
        gemm_tc_kernel<<<grid, 256, GSMEM_BYTES>>>(x, B_EXT, W0, nullptr, B_H0, n, 512, 128);
    }
    attn_coef_kernel<<<n, 128>>>(B_H0, att_src0, att_dst0, B_EXT, B_AS0, B_AD0, 4);

    cudaStreamWaitEvent((cudaStream_t)0, evJoin, 0);
    agg0_kernel<<<n, 128>>>(b0);

    // ---- layer 1: H1 = H0A @ W1^T ----
    {
        dim3 grid(128 / TBN, (n + TBM - 1) / TBM);
        gemm_tc_kernel<<<grid, 256, GSMEM_BYTES>>>(nullptr, B_H0A, W1, nullptr, B_H1, n, 128, 512);
    }
    attn_coef_kernel<<<n, 128>>>(B_H1, att_src1, att_dst1, B_EXT, B_AS1, B_AD1, 1);
    agg1_kernel<<<(n + 3) / 4, 128>>>(b1, n);

    // ---- edge scores directly from H1A: s1 = H1A.v1, s2 = H1A.v2 ----
    attn_coef_kernel<<<n, 128>>>(B_H1A, nullptr, nullptr, B_V, B_S1, B_S2, 1);

    // ---- final n x n outer sum ----
    outer_kernel<<<n, 256>>>(bedge, out, n);
}

// round 11
// speedup vs baseline: 1.5108x; 1.0598x over previous
#include <cuda_runtime.h>
#include <cuda_bf16.h>
#include <cuda_fp16.h>
#include <math.h>

// ---------------- problem constants ----------------
#define NMAX 10000
#define EMAX 320000
#define MMAX (EMAX + NMAX)   // edges + self loops

// ---------------- device scratch ----------------
__device__ __align__(16) float g_H0 [NMAX * 512];
__device__ __align__(16) float g_H0A[NMAX * 512];
__device__ __align__(16) float g_H1 [NMAX * 128];
__device__ __align__(16) float g_H1A[NMAX * 128];
__device__ __align__(16) float g_AS0[NMAX * 4];
__device__ __align__(16) float g_AD0[NMAX * 4];
__device__ __align__(16) float g_AS1[NMAX];
__device__ __align__(16) float g_AD1[NMAX];
__device__ __align__(16) float g_S1 [NMAX];
__device__ __align__(16) float g_S2 [NMAX];
__device__ __align__(16) float g_V  [260];              // v1[128], v2[128], c
__device__ __align__(16) unsigned g_H0h[NMAX * 256];    // H0 as packed half2
__device__ __align__(16) unsigned g_H1h[NMAX * 64];     // H1 as packed half2
__device__ __align__(16) int   g_deg[NMAX];
__device__ __align__(16) int   g_off[NMAX + 1];
__device__ __align__(16) int   g_cur[NMAX];
__device__ __align__(16) int   g_srt[MMAX];

// buffer ids
#define B_H0   0
#define B_H0A  1
#define B_H1   2
#define B_H1A  3
#define B_AS0  5
#define B_AD0  6
#define B_AS1  7
#define B_AD1  8
#define B_S1   9
#define B_S2   10
#define B_V    11
#define B_EXT  (-1)

// half-copy ids
#define H_NONE (-1)
#define H_H0h  0
#define H_H1h  1

__device__ __forceinline__ float* buf_sel(int id) {
    switch (id) {
        case B_H0:  return g_H0;
        case B_H0A: return g_H0A;
        case B_H1:  return g_H1;
        case B_H1A: return g_H1A;
        case B_AS0: return g_AS0;
        case B_AD0: return g_AD0;
        case B_AS1: return g_AS1;
        case B_AD1: return g_AD1;
        case B_S1:  return g_S1;
        case B_V:   return g_V;
        default:    return g_S2;
    }
}

__device__ __forceinline__ unsigned* hbuf_sel(int id) {
    return (id == H_H0h) ? g_H0h : g_H1h;
}

// ---------------- CSR build kernels ----------------
__global__ void zero_deg_kernel(int n) {
    int i = blockIdx.x * blockDim.x + threadIdx.x;
    if (i < n) g_deg[i] = 0;
}

__global__ void hist_kernel(const int* __restrict__ ei, int E, int n) {
    int e = blockIdx.x * blockDim.x + threadIdx.x;
    int M = E + n;
    if (e >= M) return;
    int dst = (e < E) ? ei[E + e] : (e - E);
    if ((unsigned)dst < (unsigned)n)
        atomicAdd(&g_deg[dst], 1);
}

__global__ void scan_kernel(int n) {
    __shared__ int sm[1024];
    int t = threadIdx.x;
    int chunk = (n + 1023) >> 10;
    int b = t * chunk;
    int e = min(n, b + chunk);
    int s = 0;
    for (int i = b; i < e; i++) s += g_deg[i];
    sm[t] = s;
    __syncthreads();
    for (int o = 1; o < 1024; o <<= 1) {
        int v = (t >= o) ? sm[t - o] : 0;
        __syncthreads();
        sm[t] += v;
        __syncthreads();
    }
    int run = sm[t] - s;
    for (int i = b; i < e; i++) {
        g_off[i] = run;
        g_cur[i] = run;
        run += g_deg[i];
    }
    if (t == 1023) g_off[n] = sm[1023];
}

__global__ void scatter_kernel(const int* __restrict__ ei, int E, int n) {
    int e = blockIdx.x * blockDim.x + threadIdx.x;
    int M = E + n;
    if (e >= M) return;
    int src, dst;
    if (e < E) { src = ei[e]; dst = ei[E + e]; }
    else       { src = e - E; dst = e - E; }
    if ((unsigned)dst >= (unsigned)n || (unsigned)src >= (unsigned)n) return;
    int pos = atomicAdd(&g_cur[dst], 1);
    if (pos < MMAX) g_srt[pos] = src;
}

// ---------------- v-vectors: v1 = Wout^T w1, v2 = Wout^T w2, c = bout.(w1+w2) ----------------
__global__ void vec_kernel(const float* __restrict__ Wout, const float* __restrict__ bout,
                           const float* __restrict__ Wedge) {
    int k = threadIdx.x;   // 128
    float a1 = 0.f, a2 = 0.f;
    for (int j = 0; j < 128; j++) {
        float wo = Wout[j * 128 + k];
        a1 += wo * Wedge[j];
        a2 += wo * Wedge[128 + j];
    }
    g_V[k] = a1;
    g_V[128 + k] = a2;
    if (k == 0) {
        float c = 0.f;
        for (int j = 0; j < 128; j++) c += bout[j] * (Wedge[j] + Wedge[128 + j]);
        g_V[256] = c;
    }
}

// ---------------- bf16x3 TC GEMM, software-pipelined double buffer ----------------
// C[M,N] = A[M,K] * B[N,K]^T (+bias); C += Ahi*Bhi + Ahi*Blo + Alo*Bhi.
// Optional secondary output: packed half2 copy of C (for fp16 gathers).
#define TBM 128
#define TBN 64
#define TBK 32
#define KP  (TBK / 2)     // 16 packed pairs
#define SSTR (KP + 4)     // 20
#define A_SZ (TBM * SSTR)
#define B_SZ (TBN * SSTR)
#define GSMEM_BYTES (2 * (A_SZ + A_SZ + B_SZ + B_SZ) * 4)  // 61440

__device__ __forceinline__ unsigned pack_bf2(float a, float b) {
    __nv_bfloat162 p = __floats2bfloat162_rn(a, b);
    return *reinterpret_cast<unsigned*>(&p);
}

__device__ __forceinline__ void mma_bf16(float acc[4], unsigned a0, unsigned a1,
                                         unsigned a2, unsigned a3,
                                         unsigned b0, unsigned b1) {
    asm volatile(
        "mma.sync.aligned.m16n8k16.row.col.f32.bf16.bf16.f32 "
        "{%0,%1,%2,%3}, {%4,%5,%6,%7}, {%8,%9}, {%0,%1,%2,%3};"
        : "+f"(acc[0]), "+f"(acc[1]), "+f"(acc[2]), "+f"(acc[3])
        : "r"(a0), "r"(a1), "r"(a2), "r"(a3), "r"(b0), "r"(b1));
}

__global__ void __launch_bounds__(256)
gemm_tc_kernel(const float* __restrict__ Aext, int aid,
               const float* __restrict__ B,
               const float* __restrict__ bias,
               int cid, int c2id, int M, int N, int K) {
    const float* A = (aid == B_EXT) ? Aext : buf_sel(aid);
    float* C = buf_sel(cid);
    unsigned* C2 = (c2id >= 0) ? hbuf_sel(c2id) : nullptr;
    int N2 = N >> 1;

    extern __shared__ unsigned smu[];
    unsigned* AsH = smu;
    unsigned* AsL = AsH + 2 * A_SZ;
    unsigned* BsH = AsL + 2 * A_SZ;
    unsigned* BsL = BsH + 2 * B_SZ;

    int tid = threadIdx.x;
    int warp = tid >> 5, lane = tid & 31;
    int wm = warp >> 2;
    int wn = warp & 3;
    int bm = blockIdx.y * TBM;
    int bn = blockIdx.x * TBN;

    int lr = tid >> 3;
    int lc = tid & 7;

    float acc[4][2][4];
#pragma unroll
    for (int mt = 0; mt < 4; mt++)
#pragma unroll
        for (int nt = 0; nt < 2; nt++)
#pragma unroll
            for (int r = 0; r < 4; r++) acc[mt][nt][r] = 0.f;

    int qrow = lane >> 2;
    int qcol = lane & 3;

    float4 ra[4], rb[2];

    auto load_tile = [&](int k0) {
#pragma unroll
        for (int i = 0; i < 4; i++) {
            int rg = bm + lr + 32 * i;
            ra[i] = make_float4(0.f, 0.f, 0.f, 0.f);
            if (rg < M) ra[i] = *(const float4*)&A[(size_t)rg * K + k0 + lc * 4];
        }
#pragma unroll
        for (int i = 0; i < 2; i++)
            rb[i] = *(const float4*)&B[(size_t)(bn + lr + 32 * i) * K + k0 + lc * 4];
    };

    auto cvt_store = [&](int buf) {
        unsigned* aH = AsH + buf * A_SZ;
        unsigned* aL = AsL + buf * A_SZ;
        unsigned* bH = BsH + buf * B_SZ;
        unsigned* bL = BsL + buf * B_SZ;
#pragma unroll
        for (int i = 0; i < 4; i++) {
            float4 v = ra[i];
            float hx = __bfloat162float(__float2bfloat16_rn(v.x));
            float hy = __bfloat162float(__float2bfloat16_rn(v.y));
            float hz = __bfloat162float(__float2bfloat16_rn(v.z));
            float hw = __bfloat162float(__float2bfloat16_rn(v.w));
            int rl = lr + 32 * i;
            unsigned* dH = &aH[rl * SSTR + lc * 2];
            unsigned* dL = &aL[rl * SSTR + lc * 2];
            dH[0] = pack_bf2(hx, hy);
            dH[1] = pack_bf2(hz, hw);
            dL[0] = pack_bf2(v.x - hx, v.y - hy);
            dL[1] = pack_bf2(v.z - hz, v.w - hw);
        }
#pragma unroll
        for (int i = 0; i < 2; i++) {
            float4 v = rb[i];
            float hx = __bfloat162float(__float2bfloat16_rn(v.x));
            float hy = __bfloat162float(__float2bfloat16_rn(v.y));
            float hz = __bfloat162float(__float2bfloat16_rn(v.z));
            float hw = __bfloat162float(__float2bfloat16_rn(v.w));
            int rl = lr + 32 * i;
            unsigned* dH = &bH[rl * SSTR + lc * 2];
            unsigned* dL = &bL[rl * SSTR + lc * 2];
            dH[0] = pack_bf2(hx, hy);
            dH[1] = pack_bf2(hz, hw);
            dL[0] = pack_bf2(v.x - hx, v.y - hy);
            dL[1] = pack_bf2(v.z - hz, v.w - hw);
        }
    };

    int nTiles = K / TBK;

    load_tile(0);
    cvt_store(0);
    __syncthreads();

    for (int kt = 0; kt < nTiles; kt++) {
        int cur = kt & 1;
        if (kt + 1 < nTiles) load_tile((kt + 1) * TBK);

        unsigned* aH = AsH + cur * A_SZ;
        unsigned* aL = AsL + cur * A_SZ;
        unsigned* bH = BsH + cur * B_SZ;
        unsigned* bL = BsL + cur * B_SZ;

#pragma unroll
        for (int ks = 0; ks < TBK / 16; ks++) {
            int kb = ks * 8;
            unsigned bh[2][2], bl[2][2];
#pragma unroll
            for (int nt = 0; nt < 2; nt++) {
                int nn = wn * 16 + nt * 8 + qrow;
                bh[nt][0] = bH[nn * SSTR + kb + qcol];
                bh[nt][1] = bH[nn * SSTR + kb + qcol + 4];
                bl[nt][0] = bL[nn * SSTR + kb + qcol];
                bl[nt][1] = bL[nn * SSTR + kb + qcol + 4];
            }
#pragma unroll
            for (int mt = 0; mt < 4; mt++) {
                int mm = wm * 64 + mt * 16 + qrow;
                unsigned ah0 = aH[mm * SSTR + kb + qcol];
                unsigned ah1 = aH[(mm + 8) * SSTR + kb + qcol];
                unsigned ah2 = aH[mm * SSTR + kb + qcol + 4];
                unsigned ah3 = aH[(mm + 8) * SSTR + kb + qcol + 4];
                unsigned al0 = aL[mm * SSTR + kb + qcol];
                unsigned al1 = aL[(mm + 8) * SSTR + kb + qcol];
                unsigned al2 = aL[mm * SSTR + kb + qcol + 4];
                unsigned al3 = aL[(mm + 8) * SSTR + kb + qcol + 4];
#pragma unroll
                for (int nt = 0; nt < 2; nt++) {
                    mma_bf16(acc[mt][nt], ah0, ah1, ah2, ah3, bh[nt][0], bh[nt][1]);
                    mma_bf16(acc[mt][nt], ah0, ah1, ah2, ah3, bl[nt][0], bl[nt][1]);
                    mma_bf16(acc[mt][nt], al0, al1, al2, al3, bh[nt][0], bh[nt][1]);
                }
            }
        }

        if (kt + 1 < nTiles) cvt_store((kt + 1) & 1);
        __syncthreads();
    }

    // epilogue: fp32 C + optional packed-half C2
#pragma unroll
    for (int mt = 0; mt < 4; mt++) {
#pragma unroll
        for (int nt = 0; nt < 2; nt++) {
            int row = bm + wm * 64 + mt * 16 + qrow;
            int col = bn + wn * 16 + nt * 8 + qcol * 2;
            float b0 = 0.f, b1 = 0.f;
            if (bias) { b0 = bias[col]; b1 = bias[col + 1]; }
            if (row < M) {
                float2 o = {acc[mt][nt][0] + b0, acc[mt][nt][1] + b1};
                *(float2*)&C[(size_t)row * N + col] = o;
                if (C2) {
                    __half2 h = __floats2half2_rn(o.x, o.y);
                    C2[(size_t)row * N2 + (col >> 1)] = *reinterpret_cast<unsigned*>(&h);
                }
            }
            if (row + 8 < M) {
                float2 o = {acc[mt][nt][2] + b0, acc[mt][nt][3] + b1};
                *(float2*)&C[(size_t)(row + 8) * N + col] = o;
                if (C2) {
                    __half2 h = __floats2half2_rn(o.x, o.y);
                    C2[(size_t)(row + 8) * N2 + (col >> 1)] = *reinterpret_cast<unsigned*>(&h);
                }
            }
        }
    }
}

// ---------------- attention coefficients ----------------
__global__ void attn_coef_kernel(int hid, const float* __restrict__ atts_ext,
                                 const float* __restrict__ attd_ext,
                                 int attid,
                                 int osid, int odid, int heads) {
    const float* H = buf_sel(hid);
    const float* atts = (attid >= 0) ? buf_sel(attid) : atts_ext;
    const float* attd = (attid >= 0) ? buf_sel(attid) + 128 : attd_ext;
    float* osrc = buf_sel(osid);
    float* odst = buf_sel(odid);

    int node = blockIdx.x;
    int t = threadIdx.x;            // 128
    int w = t >> 5, lane = t & 31;
    int Ct = heads * 128;
    float ps[4] = {0.f, 0.f, 0.f, 0.f}, pd[4] = {0.f, 0.f, 0.f, 0.f};
    for (int k = 0; k < heads; k++) {
        float h = H[(size_t)node * Ct + k * 128 + t];
        ps[k] = h * atts[k * 128 + t];
        pd[k] = h * attd[k * 128 + t];
    }
#pragma unroll
    for (int o = 16; o; o >>= 1) {
#pragma unroll
        for (int k = 0; k < 4; k++) {
            ps[k] += __shfl_xor_sync(~0u, ps[k], o);
            pd[k] += __shfl_xor_sync(~0u, pd[k], o);
        }
    }
    __shared__ float ss[4][4], sd[4][4];
    if (lane == 0) {
#pragma unroll
        for (int k = 0; k < 4; k++) { ss[w][k] = ps[k]; sd[w][k] = pd[k]; }
    }
    __syncthreads();
    if (t < heads) {
        osrc[node * heads + t] = ss[0][t] + ss[1][t] + ss[2][t] + ss[3][t];
        odst[node * heads + t] = sd[0][t] + sd[1][t] + sd[2][t] + sd[3][t];
    }
}

// ---------------- layer-0 aggregation: fp16 gather (halves LTS traffic) ----------------
__global__ void agg0_kernel(const float* __restrict__ b0) {
    int node = blockIdx.x;
    int t = threadIdx.x;            // 128
    int w = t >> 5;
    int beg = g_off[node], end = g_off[node + 1];

    float adsth = g_AD0[node * 4 + w];

    float4 acc = {0.f, 0.f, 0.f, 0.f};
    float denom = 0.f;
    for (int i = beg; i < end; i++) {
        int s = g_srt[i];
        float a = g_AS0[s * 4 + w] + adsth;
        a = (a >= 0.f) ? a : 0.2f * a;
        float ex = __expf(a);
        denom += ex;
        uint2 v = *(const uint2*)&g_H0h[(size_t)s * 256 + t * 2];
        float2 p0 = __half22float2(*reinterpret_cast<__half2*>(&v.x));
        float2 p1 = __half22float2(*reinterpret_cast<__half2*>(&v.y));
        acc.x += ex * p0.x; acc.y += ex * p0.y;
        acc.z += ex * p1.x; acc.w += ex * p1.y;
    }
    float inv = 1.f / (denom + 1e-16f);
    float4 bb = *(const float4*)&b0[t * 4];
    float4 o4;
    o4.x = acc.x * inv + bb.x;
    o4.y = acc.y * inv + bb.y;
    o4.z = acc.z * inv + bb.z;
    o4.w = acc.w * inv + bb.w;
    o4.x = (o4.x > 0.f) ? o4.x : expm1f(o4.x);
    o4.y = (o4.y > 0.f) ? o4.y : expm1f(o4.y);
    o4.z = (o4.z > 0.f) ? o4.z : expm1f(o4.z);
    o4.w = (o4.w > 0.f) ? o4.w : expm1f(o4.w);
    *(float4*)&g_H0A[(size_t)node * 512 + t * 4] = o4;
}

// ---------------- layer-1 aggregation: fp16 gather ----------------
__global__ void agg1_kernel(const float* __restrict__ b1, int n) {
    int w = threadIdx.x >> 5, lane = threadIdx.x & 31;
    int node = blockIdx.x * 4 + w;
    if (node >= n) return;
    int beg = g_off[node], end = g_off[node + 1];
    float adv = g_AD1[node];

    float4 acc = {0.f, 0.f, 0.f, 0.f};
    float denom = 0.f;
    for (int i = beg; i < end; i++) {
        int s = g_srt[i];
        float a = g_AS1[s] + adv;
        a = (a >= 0.f) ? a : 0.2f * a;
        float ex = __expf(a);
        denom += ex;
        uint2 v = *(const uint2*)&g_H1h[(size_t)s * 64 + lane * 2];
        float2 p0 = __half22float2(*reinterpret_cast<__half2*>(&v.x));
        float2 p1 = __half22float2(*reinterpret_cast<__half2*>(&v.y));
        acc.x += ex * p0.x; acc.y += ex * p0.y;
        acc.z += ex * p1.x; acc.w += ex * p1.y;
    }
    float inv = 1.f / (denom + 1e-16f);
    float4 bb = *(const float4*)&b1[lane * 4];
    float4 o4;
    o4.x = acc.x * inv + bb.x;
    o4.y = acc.y * inv + bb.y;
    o4.z = acc.z * inv + bb.z;
    o4.w = acc.w * inv + bb.w;
    o4.x = (o4.x > 0.f) ? o4.x : expm1f(o4.x);
    o4.y = (o4.y > 0.f) ? o4.y : expm1f(o4.y);
    o4.z = (o4.z > 0.f) ? o4.z : expm1f(o4.z);
    o4.w = (o4.w > 0.f) ? o4.w : expm1f(o4.w);
    *(float4*)&g_H1A[(size_t)node * 128 + lane * 4] = o4;
}

// ---------------- final outer sum ----------------
__global__ void outer_kernel(const float* __restrict__ bedge, float* __restrict__ out, int n) {
    int i = blockIdx.x;
    float v = g_S1[i] + bedge[0] + g_V[256];
    float* row = out + (size_t)i * n;
    int n4 = n >> 2;
    const float4* s24 = (const float4*)g_S2;
    for (int j = threadIdx.x; j < n4; j += blockDim.x) {
        float4 b = s24[j];
        float4 o = {v + b.x, v + b.y, v + b.z, v + b.w};
        ((float4*)row)[j] = o;
    }
    for (int j = (n4 << 2) + threadIdx.x; j < n; j += blockDim.x)
        row[j] = v + g_S2[j];
}

// ---------------- host launcher ----------------
extern "C" void kernel_launch(void* const* d_in, const int* in_sizes, int n_in,
                              void* d_out, int out_size) {
    const float* x        = (const float*)d_in[0];
    const int*   ei       = (const int*)d_in[1];     // int32
    const float* W0       = (const float*)d_in[2];
    const float* att_src0 = (const float*)d_in[3];
    const float* att_dst0 = (const float*)d_in[4];
    const float* b0       = (const float*)d_in[5];
    const float* W1       = (const float*)d_in[6];
    const float* att_src1 = (const float*)d_in[7];
    const float* att_dst1 = (const float*)d_in[8];
    const float* b1       = (const float*)d_in[9];
    const float* Wout     = (const float*)d_in[10];
    const float* bout     = (const float*)d_in[11];
    const float* Wedge    = (const float*)d_in[12];
    const float* bedge    = (const float*)d_in[13];
    float* out = (float*)d_out;

    int n = in_sizes[0] / 128;
    int E = in_sizes[1] / 2;
    int M = E + n;

    cudaFuncSetAttribute(gemm_tc_kernel,
                         cudaFuncAttributeMaxDynamicSharedMemorySize, GSMEM_BYTES);

    // Side stream: CSR chain feeds agg0 (evJoin recorded IMMEDIATELY after scatter);
    // vec_kernel runs after, joined only before the final attn_s (evJoin2).
    cudaStream_t side;
    cudaStreamCreateWithFlags(&side, cudaStreamNonBlocking);
    cudaEvent_t evFork, evJoin, evJoin2;
    cudaEventCreateWithFlags(&evFork, cudaEventDisableTiming);
    cudaEventCreateWithFlags(&evJoin, cudaEventDisableTiming);
    cudaEventCreateWithFlags(&evJoin2, cudaEventDisableTiming);

    cudaEventRecord(evFork, (cudaStream_t)0);
    cudaStreamWaitEvent(side, evFork, 0);

    zero_deg_kernel<<<(n + 255) / 256, 256, 0, side>>>(n);
    hist_kernel<<<(M + 255) / 256, 256, 0, side>>>(ei, E, n);
    scan_kernel<<<1, 1024, 0, side>>>(n);
    scatter_kernel<<<(M + 255) / 256, 256, 0, side>>>(ei, E, n);
    cudaEventRecord(evJoin, side);
    vec_kernel<<<1, 128, 0, side>>>(Wout, bout, Wedge);
    cudaEventRecord(evJoin2, side);

    // ---- layer 0: H0 = x @ W0^T (bf16x3 TC, pipelined; also writes fp16 copy) ----
    {
        dim3 grid(512 / TBN, (n + TBM - 1) / TBM);
        gemm_tc_kernel<<<grid, 256, GSMEM_BYTES>>>(x, B_EXT, W0, nullptr, B_H0, H_H0h, n, 512, 128);
    }
    attn_coef_kernel<<<n, 128>>>(B_H0, att_src0, att_dst0, B_EXT, B_AS0, B_AD0, 4);

    cudaStreamWaitEvent((cudaStream_t)0, evJoin, 0);
    agg0_kernel<<<n, 128>>>(b0);

    // ---- layer 1: H1 = H0A @ W1^T (also writes fp16 copy) ----
    {
        dim3 grid(128 / TBN, (n + TBM - 1) / TBM);
        gemm_tc_kernel<<<grid, 256, GSMEM_BYTES>>>(nullptr, B_H0A, W1, nullptr, B_H1, H_H1h, n, 128, 512);
    }
    attn_coef_kernel<<<n, 128>>>(B_H1, att_src1, att_dst1, B_EXT, B_AS1, B_AD1, 1);
    agg1_kernel<<<(n + 3) / 4, 128>>>(b1, n);

    // ---- edge scores: s1 = H1A.v1, s2 = H1A.v2 ----
    cudaStreamWaitEvent((cudaStream_t)0, evJoin2, 0);
    attn_coef_kernel<<<n, 128>>>(B_H1A, nullptr, nullptr, B_V, B_S1, B_S2, 1);

    // ---- final n x n outer sum ----
    outer_kernel<<<n, 256>>>(bedge, out, n);
}

// round 12
// speedup vs baseline: 1.6084x; 1.0646x over previous
#include <cuda_runtime.h>
#include <cuda_bf16.h>
#include <cuda_fp16.h>
#include <math.h>

// ---------------- problem constants ----------------
#define NMAX 10000
#define EMAX 320000
#define MMAX (EMAX + NMAX)   // edges + self loops

// ---------------- device scratch ----------------
__device__ __align__(16) float g_H0 [NMAX * 512];
__device__ __align__(16) float g_H0A[NMAX * 512];
__device__ __align__(16) float g_H1 [NMAX * 128];
__device__ __align__(16) float g_AS0[NMAX * 4];
__device__ __align__(16) float g_AD0[NMAX * 4];
__device__ __align__(16) float g_AS1[NMAX];
__device__ __align__(16) float g_AD1[NMAX];
__device__ __align__(16) float g_S1 [NMAX];
__device__ __align__(16) float g_S2 [NMAX];
__device__ __align__(16) float g_V  [260];              // v1[128], v2[128], c
__device__ __align__(16) unsigned g_H0h[NMAX * 256];    // H0 as packed half2
__device__ __align__(16) unsigned g_H1h[NMAX * 64];     // H1 as packed half2
__device__ __align__(16) int   g_deg[NMAX];
__device__ __align__(16) int   g_off[NMAX + 1];
__device__ __align__(16) int   g_cur[NMAX];
__device__ __align__(16) int   g_srt[MMAX];

// buffer ids
#define B_H0   0
#define B_H0A  1
#define B_H1   2
#define B_AS0  5
#define B_AD0  6
#define B_AS1  7
#define B_AD1  8
#define B_S1   9
#define B_S2   10
#define B_V    11
#define B_EXT  (-1)

// half-copy ids
#define H_NONE (-1)
#define H_H0h  0
#define H_H1h  1

__device__ __forceinline__ float* buf_sel(int id) {
    switch (id) {
        case B_H0:  return g_H0;
        case B_H0A: return g_H0A;
        case B_H1:  return g_H1;
        case B_AS0: return g_AS0;
        case B_AD0: return g_AD0;
        case B_AS1: return g_AS1;
        case B_AD1: return g_AD1;
        case B_S1:  return g_S1;
        case B_V:   return g_V;
        default:    return g_S2;
    }
}

__device__ __forceinline__ unsigned* hbuf_sel(int id) {
    return (id == H_H0h) ? g_H0h : g_H1h;
}

// ---------------- CSR build kernels ----------------
__global__ void zero_deg_kernel(int n) {
    int i = blockIdx.x * blockDim.x + threadIdx.x;
    if (i < n) g_deg[i] = 0;
}

__global__ void hist_kernel(const int* __restrict__ ei, int E, int n) {
    int e = blockIdx.x * blockDim.x + threadIdx.x;
    int M = E + n;
    if (e >= M) return;
    int dst = (e < E) ? ei[E + e] : (e - E);
    if ((unsigned)dst < (unsigned)n)
        atomicAdd(&g_deg[dst], 1);
}

__global__ void scan_kernel(int n) {
    __shared__ int sm[1024];
    int t = threadIdx.x;
    int chunk = (n + 1023) >> 10;
    int b = t * chunk;
    int e = min(n, b + chunk);
    int s = 0;
    for (int i = b; i < e; i++) s += g_deg[i];
    sm[t] = s;
    __syncthreads();
    for (int o = 1; o < 1024; o <<= 1) {
        int v = (t >= o) ? sm[t - o] : 0;
        __syncthreads();
        sm[t] += v;
        __syncthreads();
    }
    int run = sm[t] - s;
    for (int i = b; i < e; i++) {
        g_off[i] = run;
        g_cur[i] = run;
        run += g_deg[i];
    }
    if (t == 1023) g_off[n] = sm[1023];
}

__global__ void scatter_kernel(const int* __restrict__ ei, int E, int n) {
    int e = blockIdx.x * blockDim.x + threadIdx.x;
    int M = E + n;
    if (e >= M) return;
    int src, dst;
    if (e < E) { src = ei[e]; dst = ei[E + e]; }
    else       { src = e - E; dst = e - E; }
    if ((unsigned)dst >= (unsigned)n || (unsigned)src >= (unsigned)n) return;
    int pos = atomicAdd(&g_cur[dst], 1);
    if (pos < MMAX) g_srt[pos] = src;
}

// ---------------- v-vectors: v1 = Wout^T w1, v2 = Wout^T w2, c = bout.(w1+w2) ----------------
__global__ void vec_kernel(const float* __restrict__ Wout, const float* __restrict__ bout,
                           const float* __restrict__ Wedge) {
    int k = threadIdx.x;   // 128
    float a1 = 0.f, a2 = 0.f;
    for (int j = 0; j < 128; j++) {
        float wo = Wout[j * 128 + k];
        a1 += wo * Wedge[j];
        a2 += wo * Wedge[128 + j];
    }
    g_V[k] = a1;
    g_V[128 + k] = a2;
    if (k == 0) {
        float c = 0.f;
        for (int j = 0; j < 128; j++) c += bout[j] * (Wedge[j] + Wedge[128 + j]);
        g_V[256] = c;
    }
}

// ---------------- bf16x3 TC GEMM, software-pipelined double buffer ----------------
#define TBM 128
#define TBN 64
#define TBK 32
#define KP  (TBK / 2)
#define SSTR (KP + 4)     // 20
#define A_SZ (TBM * SSTR)
#define B_SZ (TBN * SSTR)
#define GSMEM_BYTES (2 * (A_SZ + A_SZ + B_SZ + B_SZ) * 4)  // 61440

__device__ __forceinline__ unsigned pack_bf2(float a, float b) {
    __nv_bfloat162 p = __floats2bfloat162_rn(a, b);
    return *reinterpret_cast<unsigned*>(&p);
}

__device__ __forceinline__ void mma_bf16(float acc[4], unsigned a0, unsigned a1,
                                         unsigned a2, unsigned a3,
                                         unsigned b0, unsigned b1) {
    asm volatile(
        "mma.sync.aligned.m16n8k16.row.col.f32.bf16.bf16.f32 "
        "{%0,%1,%2,%3}, {%4,%5,%6,%7}, {%8,%9}, {%0,%1,%2,%3};"
        : "+f"(acc[0]), "+f"(acc[1]), "+f"(acc[2]), "+f"(acc[3])
        : "r"(a0), "r"(a1), "r"(a2), "r"(a3), "r"(b0), "r"(b1));
}

__global__ void __launch_bounds__(256)
gemm_tc_kernel(const float* __restrict__ Aext, int aid,
               const float* __restrict__ B,
               const float* __restrict__ bias,
               int cid, int c2id, int M, int N, int K) {
    const float* A = (aid == B_EXT) ? Aext : buf_sel(aid);
    float* C = buf_sel(cid);
    unsigned* C2 = (c2id >= 0) ? hbuf_sel(c2id) : nullptr;
    int N2 = N >> 1;

    extern __shared__ unsigned smu[];
    unsigned* AsH = smu;
    unsigned* AsL = AsH + 2 * A_SZ;
    unsigned* BsH = AsL + 2 * A_SZ;
    unsigned* BsL = BsH + 2 * B_SZ;

    int tid = threadIdx.x;
    int warp = tid >> 5, lane = tid & 31;
    int wm = warp >> 2;
    int wn = warp & 3;
    int bm = blockIdx.y * TBM;
    int bn = blockIdx.x * TBN;

    int lr = tid >> 3;
    int lc = tid & 7;

    float acc[4][2][4];
#pragma unroll
    for (int mt = 0; mt < 4; mt++)
#pragma unroll
        for (int nt = 0; nt < 2; nt++)
#pragma unroll
            for (int r = 0; r < 4; r++) acc[mt][nt][r] = 0.f;

    int qrow = lane >> 2;
    int qcol = lane & 3;

    float4 ra[4], rb[2];

    auto load_tile = [&](int k0) {
#pragma unroll
        for (int i = 0; i < 4; i++) {
            int rg = bm + lr + 32 * i;
            ra[i] = make_float4(0.f, 0.f, 0.f, 0.f);
            if (rg < M) ra[i] = *(const float4*)&A[(size_t)rg * K + k0 + lc * 4];
        }
#pragma unroll
        for (int i = 0; i < 2; i++)
            rb[i] = *(const float4*)&B[(size_t)(bn + lr + 32 * i) * K + k0 + lc * 4];
    };

    auto cvt_store = [&](int buf) {
        unsigned* aH = AsH + buf * A_SZ;
        unsigned* aL = AsL + buf * A_SZ;
        unsigned* bH = BsH + buf * B_SZ;
        unsigned* bL = BsL + buf * B_SZ;
#pragma unroll
        for (int i = 0; i < 4; i++) {
            float4 v = ra[i];
            float hx = __bfloat162float(__float2bfloat16_rn(v.x));
            float hy = __bfloat162float(__float2bfloat16_rn(v.y));
            float hz = __bfloat162float(__float2bfloat16_rn(v.z));
            float hw = __bfloat162float(__float2bfloat16_rn(v.w));
            int rl = lr + 32 * i;
            unsigned* dH = &aH[rl * SSTR + lc * 2];
            unsigned* dL = &aL[rl * SSTR + lc * 2];
            dH[0] = pack_bf2(hx, hy);
            dH[1] = pack_bf2(hz, hw);
            dL[0] = pack_bf2(v.x - hx, v.y - hy);
            dL[1] = pack_bf2(v.z - hz, v.w - hw);
        }
#pragma unroll
        for (int i = 0; i < 2; i++) {
            float4 v = rb[i];
            float hx = __bfloat162float(__float2bfloat16_rn(v.x));
            float hy = __bfloat162float(__float2bfloat16_rn(v.y));
            float hz = __bfloat162float(__float2bfloat16_rn(v.z));
            float hw = __bfloat162float(__float2bfloat16_rn(v.w));
            int rl = lr + 32 * i;
            unsigned* dH = &bH[rl * SSTR + lc * 2];
            unsigned* dL = &bL[rl * SSTR + lc * 2];
            dH[0] = pack_bf2(hx, hy);
            dH[1] = pack_bf2(hz, hw);
            dL[0] = pack_bf2(v.x - hx, v.y - hy);
            dL[1] = pack_bf2(v.z - hz, v.w - hw);
        }
    };

    int nTiles = K / TBK;

    load_tile(0);
    cvt_store(0);
    __syncthreads();

    for (int kt = 0; kt < nTiles; kt++) {
        int cur = kt & 1;
        if (kt + 1 < nTiles) load_tile((kt + 1) * TBK);

        unsigned* aH = AsH + cur * A_SZ;
        unsigned* aL = AsL + cur * A_SZ;
        unsigned* bH = BsH + cur * B_SZ;
        unsigned* bL = BsL + cur * B_SZ;

#pragma unroll
        for (int ks = 0; ks < TBK / 16; ks++) {
            int kb = ks * 8;
            unsigned bh[2][2], bl[2][2];
#pragma unroll
            for (int nt = 0; nt < 2; nt++) {
                int nn = wn * 16 + nt * 8 + qrow;
                bh[nt][0] = bH[nn * SSTR + kb + qcol];
                bh[nt][1] = bH[nn * SSTR + kb + qcol + 4];
                bl[nt][0] = bL[nn * SSTR + kb + qcol];
                bl[nt][1] = bL[nn * SSTR + kb + qcol + 4];
            }
#pragma unroll
            for (int mt = 0; mt < 4; mt++) {
                int mm = wm * 64 + mt * 16 + qrow;
                unsigned ah0 = aH[mm * SSTR + kb + qcol];
                unsigned ah1 = aH[(mm + 8) * SSTR + kb + qcol];
                unsigned ah2 = aH[mm * SSTR + kb + qcol + 4];
                unsigned ah3 = aH[(mm + 8) * SSTR + kb + qcol + 4];
                unsigned al0 = aL[mm * SSTR + kb + qcol];
                unsigned al1 = aL[(mm + 8) * SSTR + kb + qcol];
                unsigned al2 = aL[mm * SSTR + kb + qcol + 4];
                unsigned al3 = aL[(mm + 8) * SSTR + kb + qcol + 4];
#pragma unroll
                for (int nt = 0; nt < 2; nt++) {
                    mma_bf16(acc[mt][nt], ah0, ah1, ah2, ah3, bh[nt][0], bh[nt][1]);
                    mma_bf16(acc[mt][nt], ah0, ah1, ah2, ah3, bl[nt][0], bl[nt][1]);
                    mma_bf16(acc[mt][nt], al0, al1, al2, al3, bh[nt][0], bh[nt][1]);
                }
            }
        }

        if (kt + 1 < nTiles) cvt_store((kt + 1) & 1);
        __syncthreads();
    }

    // epilogue: fp32 C + optional packed-half C2
#pragma unroll
    for (int mt = 0; mt < 4; mt++) {
#pragma unroll
        for (int nt = 0; nt < 2; nt++) {
            int row = bm + wm * 64 + mt * 16 + qrow;
            int col = bn + wn * 16 + nt * 8 + qcol * 2;
            float b0 = 0.f, b1 = 0.f;
            if (bias) { b0 = bias[col]; b1 = bias[col + 1]; }
            if (row < M) {
                float2 o = {acc[mt][nt][0] + b0, acc[mt][nt][1] + b1};
                *(float2*)&C[(size_t)row * N + col] = o;
                if (C2) {
                    __half2 h = __floats2half2_rn(o.x, o.y);
                    C2[(size_t)row * N2 + (col >> 1)] = *reinterpret_cast<unsigned*>(&h);
                }
            }
            if (row + 8 < M) {
                float2 o = {acc[mt][nt][2] + b0, acc[mt][nt][3] + b1};
                *(float2*)&C[(size_t)(row + 8) * N + col] = o;
                if (C2) {
                    __half2 h = __floats2half2_rn(o.x, o.y);
                    C2[(size_t)(row + 8) * N2 + (col >> 1)] = *reinterpret_cast<unsigned*>(&h);
                }
            }
        }
    }
}

// ---------------- attention coefficients ----------------
__global__ void attn_coef_kernel(int hid, const float* __restrict__ atts_ext,
                                 const float* __restrict__ attd_ext,
                                 int osid, int odid, int heads) {
    const float* H = buf_sel(hid);
    const float* atts = atts_ext;
    const float* attd = attd_ext;
    float* osrc = buf_sel(osid);
    float* odst = buf_sel(odid);

    int node = blockIdx.x;
    int t = threadIdx.x;            // 128
    int w = t >> 5, lane = t & 31;
    int Ct = heads * 128;
    float ps[4] = {0.f, 0.f, 0.f, 0.f}, pd[4] = {0.f, 0.f, 0.f, 0.f};
    for (int k = 0; k < heads; k++) {
        float h = H[(size_t)node * Ct + k * 128 + t];
        ps[k] = h * atts[k * 128 + t];
        pd[k] = h * attd[k * 128 + t];
    }
#pragma unroll
    for (int o = 16; o; o >>= 1) {
#pragma unroll
        for (int k = 0; k < 4; k++) {
            ps[k] += __shfl_xor_sync(~0u, ps[k], o);
            pd[k] += __shfl_xor_sync(~0u, pd[k], o);
        }
    }
    __shared__ float ss[4][4], sd[4][4];
    if (lane == 0) {
#pragma unroll
        for (int k = 0; k < 4; k++) { ss[w][k] = ps[k]; sd[w][k] = pd[k]; }
    }
    __syncthreads();
    if (t < heads) {
        osrc[node * heads + t] = ss[0][t] + ss[1][t] + ss[2][t] + ss[3][t];
        odst[node * heads + t] = sd[0][t] + sd[1][t] + sd[2][t] + sd[3][t];
    }
}

// ---------------- layer-0 aggregation: fp16 gather ----------------
__global__ void agg0_kernel(const float* __restrict__ b0) {
    int node = blockIdx.x;
    int t = threadIdx.x;            // 128
    int w = t >> 5;
    int beg = g_off[node], end = g_off[node + 1];

    float adsth = g_AD0[node * 4 + w];

    float4 acc = {0.f, 0.f, 0.f, 0.f};
    float denom = 0.f;
#pragma unroll 2
    for (int i = beg; i < end; i++) {
        int s = g_srt[i];
        float a = g_AS0[s * 4 + w] + adsth;
        a = (a >= 0.f) ? a : 0.2f * a;
        float ex = __expf(a);
        denom += ex;
        uint2 v = *(const uint2*)&g_H0h[(size_t)s * 256 + t * 2];
        float2 p0 = __half22float2(*reinterpret_cast<__half2*>(&v.x));
        float2 p1 = __half22float2(*reinterpret_cast<__half2*>(&v.y));
        acc.x += ex * p0.x; acc.y += ex * p0.y;
        acc.z += ex * p1.x; acc.w += ex * p1.y;
    }
    float inv = 1.f / (denom + 1e-16f);
    float4 bb = *(const float4*)&b0[t * 4];
    float4 o4;
    o4.x = acc.x * inv + bb.x;
    o4.y = acc.y * inv + bb.y;
    o4.z = acc.z * inv + bb.z;
    o4.w = acc.w * inv + bb.w;
    o4.x = (o4.x > 0.f) ? o4.x : expm1f(o4.x);
    o4.y = (o4.y > 0.f) ? o4.y : expm1f(o4.y);
    o4.z = (o4.z > 0.f) ? o4.z : expm1f(o4.z);
    o4.w = (o4.w > 0.f) ? o4.w : expm1f(o4.w);
    *(float4*)&g_H0A[(size_t)node * 512 + t * 4] = o4;
}

// ---------------- layer-1 aggregation, fused with edge-score dots ----------------
// Computes h1a = elu(agg + b1), then S1[node]=h1a.v1, S2[node]=h1a.v2 in-register.
__global__ void agg1_kernel(const float* __restrict__ b1, int n) {
    int w = threadIdx.x >> 5, lane = threadIdx.x & 31;
    int node = blockIdx.x * 4 + w;
    if (node >= n) return;
    int beg = g_off[node], end = g_off[node + 1];
    float adv = g_AD1[node];

    float4 acc = {0.f, 0.f, 0.f, 0.f};
    float denom = 0.f;
#pragma unroll 2
    for (int i = beg; i < end; i++) {
        int s = g_srt[i];
        float a = g_AS1[s] + adv;
        a = (a >= 0.f) ? a : 0.2f * a;
        float ex = __expf(a);
        denom += ex;
        uint2 v = *(const uint2*)&g_H1h[(size_t)s * 64 + lane * 2];
        float2 p0 = __half22float2(*reinterpret_cast<__half2*>(&v.x));
        float2 p1 = __half22float2(*reinterpret_cast<__half2*>(&v.y));
        acc.x += ex * p0.x; acc.y += ex * p0.y;
        acc.z += ex * p1.x; acc.w += ex * p1.y;
    }
    float inv = 1.f / (denom + 1e-16f);
    float4 bb = *(const float4*)&b1[lane * 4];
    float4 o4;
    o4.x = acc.x * inv + bb.x;
    o4.y = acc.y * inv + bb.y;
    o4.z = acc.z * inv + bb.z;
    o4.w = acc.w * inv + bb.w;
    o4.x = (o4.x > 0.f) ? o4.x : expm1f(o4.x);
    o4.y = (o4.y > 0.f) ? o4.y : expm1f(o4.y);
    o4.z = (o4.z > 0.f) ? o4.z : expm1f(o4.z);
    o4.w = (o4.w > 0.f) ? o4.w : expm1f(o4.w);

    // fused edge-score dots: s1 = h1a . v1, s2 = h1a . v2
    float4 v1 = *(const float4*)&g_V[lane * 4];
    float4 v2 = *(const float4*)&g_V[128 + lane * 4];
    float d1 = o4.x * v1.x + o4.y * v1.y + o4.z * v1.z + o4.w * v1.w;
    float d2 = o4.x * v2.x + o4.y * v2.y + o4.z * v2.z + o4.w * v2.w;
#pragma unroll
    for (int o = 16; o; o >>= 1) {
        d1 += __shfl_xor_sync(~0u, d1, o);
        d2 += __shfl_xor_sync(~0u, d2, o);
    }
    if (lane == 0) {
        g_S1[node] = d1;
        g_S2[node] = d2;
    }
}

// ---------------- final outer sum: out[i*n+j] = s1[i] + s2[j] + c + bedge ----------------
__global__ void outer_kernel(const float* __restrict__ bedge, float* __restrict__ out, int n) {
    int i = blockIdx.x;
    float v = g_S1[i] + bedge[0] + g_V[256];
    float* row = out + (size_t)i * n;
    int n4 = n >> 2;
    const float4* s24 = (const float4*)g_S2;
    for (int j = threadIdx.x; j < n4; j += blockDim.x) {
        float4 b = s24[j];
        float4 o = {v + b.x, v + b.y, v + b.z, v + b.w};
        __stcs(&((float4*)row)[j], o);
    }
    for (int j = (n4 << 2) + threadIdx.x; j < n; j += blockDim.x)
        row[j] = v + g_S2[j];
}

// ---------------- host launcher ----------------
extern "C" void kernel_launch(void* const* d_in, const int* in_sizes, int n_in,
                              void* d_out, int out_size) {
    const float* x        = (const float*)d_in[0];
    const int*   ei       = (const int*)d_in[1];     // int32
    const float* W0       = (const float*)d_in[2];
    const float* att_src0 = (const float*)d_in[3];
    const float* att_dst0 = (const float*)d_in[4];
    const float* b0       = (const float*)d_in[5];
    const float* W1       = (const float*)d_in[6];
    const float* att_src1 = (const float*)d_in[7];
    const float* att_dst1 = (const float*)d_in[8];
    const float* b1       = (const float*)d_in[9];
    const float* Wout     = (const float*)d_in[10];
    const float* bout     = (const float*)d_in[11];
    const float* Wedge    = (const float*)d_in[12];
    const float* bedge    = (const float*)d_in[13];
    float* out = (float*)d_out;

    int n = in_sizes[0] / 128;
    int E = in_sizes[1] / 2;
    int M = E + n;

    cudaFuncSetAttribute(gemm_tc_kernel,
                         cudaFuncAttributeMaxDynamicSharedMemorySize, GSMEM_BYTES);

    // Side stream: CSR chain feeds agg0 (evJoin right after scatter);
    // vec_kernel joins before agg1 (its consumer via the fused dot).
    cudaStream_t side;
    cudaStreamCreateWithFlags(&side, cudaStreamNonBlocking);
    cudaEvent_t evFork, evJoin, evJoin2;
    cudaEventCreateWithFlags(&evFork, cudaEventDisableTiming);
    cudaEventCreateWithFlags(&evJoin, cudaEventDisableTiming);
    cudaEventCreateWithFlags(&evJoin2, cudaEventDisableTiming);

    cudaEventRecord(evFork, (cudaStream_t)0);
    cudaStreamWaitEvent(side, evFork, 0);

    zero_deg_kernel<<<(n + 255) / 256, 256, 0, side>>>(n);
    hist_kernel<<<(M + 255) / 256, 256, 0, side>>>(ei, E, n);
    scan_kernel<<<1, 1024, 0, side>>>(n);
    scatter_kernel<<<(M + 255) / 256, 256, 0, side>>>(ei, E, n);
    cudaEventRecord(evJoin, side);
    vec_kernel<<<1, 128, 0, side>>>(Wout, bout, Wedge);
    cudaEventRecord(evJoin2, side);

    // ---- layer 0: H0 = x @ W0^T (bf16x3 TC, pipelined; also writes fp16 copy) ----
    {
        dim3 grid(512 / TBN, (n + TBM - 1) / TBM);
        gemm_tc_kernel<<<grid, 256, GSMEM_BYTES>>>(x, B_EXT, W0, nullptr, B_H0, H_H0h, n, 512, 128);
    }
    attn_coef_kernel<<<n, 128>>>(B_H0, att_src0, att_dst0, B_AS0, B_AD0, 4);

    cudaStreamWaitEvent((cudaStream_t)0, evJoin, 0);
    agg0_kernel<<<n, 128>>>(b0);

    // ---- layer 1: H1 = H0A @ W1^T (also writes fp16 copy) ----
    {
        dim3 grid(128 / TBN, (n + TBM - 1) / TBM);
        gemm_tc_kernel<<<grid, 256, GSMEM_BYTES>>>(nullptr, B_H0A, W1, nullptr, B_H1, H_H1h, n, 128, 512);
    }
    attn_coef_kernel<<<n, 128>>>(B_H1, att_src1, att_dst1, B_AS1, B_AD1, 1);

    // agg1 consumes g_V (fused edge-score dots) -> join vec first
    cudaStreamWaitEvent((cudaStream_t)0, evJoin2, 0);
    agg1_kernel<<<(n + 3) / 4, 128>>>(b1, n);

    // ---- final n x n outer sum ----
    outer_kernel<<<n, 512>>>(bedge, out, n);
}